// round 1
// baseline (speedup 1.0000x reference)
#include <cuda_runtime.h>
#include <cuda_bf16.h>

// ---------------- problem constants ----------------
#define T_TOK   8192      // B*S
#define SEQ     2048
#define NBATCH  4
#define DIM     1024
#define NHEADS  16
#define HDIM    64
#define LATENT  128
#define QRANK   256

// ---------------- scratch (device globals; no allocation) ----------------
__device__ float g_lat [T_TOK * LATENT];        //  4 MB
__device__ float g_kvup[T_TOK * 2 * DIM];       // 64 MB  [K(1024) | V(1024)] per token
__device__ float g_qc  [T_TOK * QRANK];         //  8 MB
__device__ float g_q   [T_TOK * DIM];           // 32 MB
__device__ float g_ctx [T_TOK * DIM];           // 32 MB

// ---------------- generic tiled fp32 GEMM: C = A[M,K] @ W[K,N] + bias ----------------
// 256 threads as 16x16; thread computes TM x TN microtile. BM=16*TM, BN=16*TN, BK=16.
template<int TM, int TN>
__global__ __launch_bounds__(256, 2)
void gemm_bias_kernel(const float* __restrict__ A, const float* __restrict__ W,
                      const float* __restrict__ bias, float* __restrict__ C,
                      int M, int N, int K)
{
    constexpr int BM = TM * 16;
    constexpr int BN = TN * 16;
    constexpr int BK = 16;

    __shared__ float As[BK][BM];   // A tile stored transposed: As[k][m]
    __shared__ float Bs[BK][BN];   // B tile: Bs[k][n]

    const int tid = threadIdx.x;
    const int tr  = tid >> 4;      // 0..15
    const int tc  = tid & 15;      // 0..15
    const int m0  = blockIdx.y * BM;
    const int n0  = blockIdx.x * BN;

    float acc[TM][TN];
#pragma unroll
    for (int i = 0; i < TM; i++)
#pragma unroll
        for (int j = 0; j < TN; j++) acc[i][j] = 0.f;

    for (int k0 = 0; k0 < K; k0 += BK) {
        // load A tile (BM x 16) as float4, scatter transposed
        for (int i = tid; i < BM * 4; i += 256) {
            int r  = i >> 2;
            int cv = i & 3;
            float4 a = *(const float4*)&A[(size_t)(m0 + r) * K + k0 + cv * 4];
            As[cv * 4 + 0][r] = a.x;
            As[cv * 4 + 1][r] = a.y;
            As[cv * 4 + 2][r] = a.z;
            As[cv * 4 + 3][r] = a.w;
        }
        // load B tile (16 x BN) as float4, direct
        for (int i = tid; i < BN * 4; i += 256) {
            int r  = i / (BN / 4);
            int cv = i % (BN / 4);
            *(float4*)&Bs[r][cv * 4] = *(const float4*)&W[(size_t)(k0 + r) * N + n0 + cv * 4];
        }
        __syncthreads();

#pragma unroll
        for (int k = 0; k < BK; k++) {
            float af[TM], bf[TN];
#pragma unroll
            for (int i = 0; i < TM; i += 4)
                *(float4*)&af[i] = *(float4*)&As[k][TM * tr + i];
#pragma unroll
            for (int j = 0; j < TN; j += 4)
                *(float4*)&bf[j] = *(float4*)&Bs[k][TN * tc + j];
#pragma unroll
            for (int i = 0; i < TM; i++)
#pragma unroll
                for (int j = 0; j < TN; j++)
                    acc[i][j] = fmaf(af[i], bf[j], acc[i][j]);
        }
        __syncthreads();
    }

#pragma unroll
    for (int i = 0; i < TM; i++) {
        size_t row = (size_t)(m0 + TM * tr + i) * N + n0 + TN * tc;
#pragma unroll
        for (int j = 0; j < TN; j++)
            C[row + j] = acc[i][j] + bias[n0 + TN * tc + j];
    }
}

// ---------------- causal flash attention, fp32, hd=64 ----------------
// grid = (S/64, H, B), block = 256 (16x16 threads)
// smem layout (padded stride 68 keeps float4 alignment, avoids worst bank conflicts):
//   Qt[64][68] : Q^T   (Qt[d][qrow]), pre-scaled by 1/sqrt(64)
//   Kt[64][68] : K^T   (Kt[d][kvrow])
//   Vv[64][68] : V     (Vv[kvrow][d])
//   ST[64][68] : S^T/P^T (ST[kvcol][qrow])
//   mrow/lrow/arow[64] : running max / sum / rescale
#define APAD 68
__global__ __launch_bounds__(256)
void flash_attn_kernel(const float* __restrict__ Q, const float* __restrict__ KV,
                       float* __restrict__ Ctx)
{
    const int qt = blockIdx.x;       // q tile
    const int h  = blockIdx.y;
    const int b  = blockIdx.z;
    const int q0 = qt * 64;
    const int tid = threadIdx.x;
    const int tr = tid >> 4;         // 0..15
    const int tc = tid & 15;         // 0..15

    extern __shared__ float sm[];
    float* Qt   = sm;
    float* Kt   = Qt + 64 * APAD;
    float* Vv   = Kt + 64 * APAD;
    float* ST   = Vv + 64 * APAD;
    float* mrow = ST + 64 * APAD;
    float* lrow = mrow + 64;
    float* arow = lrow + 64;

    const float scale = 0.125f;      // 1/sqrt(64)
    const size_t qbase = ((size_t)(b * SEQ + q0)) * DIM + h * HDIM;

    for (int i = tid; i < 64 * 64; i += 256) {
        int r = i >> 6, d = i & 63;
        Qt[d * APAD + r] = Q[qbase + (size_t)r * DIM + d] * scale;
    }
    if (tid < 64) { mrow[tid] = -3.0e38f; lrow[tid] = 0.f; }

    float oacc[4][4];
#pragma unroll
    for (int i = 0; i < 4; i++)
#pragma unroll
        for (int j = 0; j < 4; j++) oacc[i][j] = 0.f;

    const int ntiles = qt + 1;       // causal: only kv tiles <= q tile
    for (int kt = 0; kt < ntiles; kt++) {
        const int k0 = kt * 64;
        const size_t kbase = ((size_t)(b * SEQ + k0)) * (2 * DIM) + h * HDIM;

        __syncthreads();  // protect prev-iter ST/K/V consumers (and first-iter Qt/mrow)

        // K tile, transposed store
        for (int i = tid; i < 64 * 64; i += 256) {
            int r = i >> 6, d = i & 63;
            Kt[d * APAD + r] = KV[kbase + (size_t)r * (2 * DIM) + d];
        }
        // V tile, direct float4
        for (int i = tid; i < 64 * 16; i += 256) {
            int r = i >> 4, dv = i & 15;
            float4 v = *(const float4*)&KV[kbase + DIM + (size_t)r * (2 * DIM) + dv * 4];
            *(float4*)&Vv[r * APAD + dv * 4] = v;
        }
        __syncthreads();

        // S^T microtile: sacc[i][j] = S[kv = 4tr+i][q = 4tc+j]
        float sacc[4][4];
#pragma unroll
        for (int i = 0; i < 4; i++)
#pragma unroll
            for (int j = 0; j < 4; j++) sacc[i][j] = 0.f;

#pragma unroll 8
        for (int d = 0; d < 64; d++) {
            float4 kf = *(float4*)&Kt[d * APAD + 4 * tr];
            float4 qf = *(float4*)&Qt[d * APAD + 4 * tc];
            const float* kp = &kf.x;
            const float* qp = &qf.x;
#pragma unroll
            for (int i = 0; i < 4; i++)
#pragma unroll
                for (int j = 0; j < 4; j++)
                    sacc[i][j] = fmaf(kp[i], qp[j], sacc[i][j]);
        }

        const bool diag = (kt == qt);
#pragma unroll
        for (int i = 0; i < 4; i++)
#pragma unroll
            for (int j = 0; j < 4; j++) {
                float s = sacc[i][j];
                if (diag && (4 * tr + i) > (4 * tc + j)) s = -3.0e38f;
                ST[(4 * tr + i) * APAD + 4 * tc + j] = s;
            }
        __syncthreads();

        // online softmax stats: 4 threads per q row
        {
            int r = tid >> 2, sub = tid & 3;
            float mx = -3.0e38f;
#pragma unroll
            for (int jj = 0; jj < 16; jj++)
                mx = fmaxf(mx, ST[(sub * 16 + jj) * APAD + r]);
            mx = fmaxf(mx, __shfl_xor_sync(0xffffffffu, mx, 1));
            mx = fmaxf(mx, __shfl_xor_sync(0xffffffffu, mx, 2));
            float mold = mrow[r];
            float mnew = fmaxf(mold, mx);
            float sum = 0.f;
#pragma unroll
            for (int jj = 0; jj < 16; jj++) {
                float* p = &ST[(sub * 16 + jj) * APAD + r];
                float e = __expf(*p - mnew);
                *p = e;
                sum += e;
            }
            sum += __shfl_xor_sync(0xffffffffu, sum, 1);
            sum += __shfl_xor_sync(0xffffffffu, sum, 2);
            if (sub == 0) {
                float al = __expf(mold - mnew);
                arow[r] = al;
                lrow[r] = lrow[r] * al + sum;
                mrow[r] = mnew;
            }
        }
        __syncthreads();

        // rescale + P@V : oacc[i][j] covers q rows 4tr+i, d cols 4tc+j
        float al[4];
#pragma unroll
        for (int i = 0; i < 4; i++) al[i] = arow[4 * tr + i];
#pragma unroll
        for (int i = 0; i < 4; i++)
#pragma unroll
            for (int j = 0; j < 4; j++) oacc[i][j] *= al[i];

#pragma unroll 8
        for (int kv = 0; kv < 64; kv++) {
            float4 pf = *(float4*)&ST[kv * APAD + 4 * tr];
            float4 vf = *(float4*)&Vv[kv * APAD + 4 * tc];
            const float* pp = &pf.x;
            const float* vp = &vf.x;
#pragma unroll
            for (int i = 0; i < 4; i++)
#pragma unroll
                for (int j = 0; j < 4; j++)
                    oacc[i][j] = fmaf(pp[i], vp[j], oacc[i][j]);
        }
    }

    // epilogue: normalize and write ctx[(b, q0+row), h*64 + col]
    float linv[4];
#pragma unroll
    for (int i = 0; i < 4; i++) linv[i] = 1.f / lrow[4 * tr + i];
#pragma unroll
    for (int i = 0; i < 4; i++) {
        size_t row = ((size_t)(b * SEQ + q0 + 4 * tr + i)) * DIM + h * HDIM + 4 * tc;
        float4 o;
        o.x = oacc[i][0] * linv[i];
        o.y = oacc[i][1] * linv[i];
        o.z = oacc[i][2] * linv[i];
        o.w = oacc[i][3] * linv[i];
        *(float4*)&Ctx[row] = o;
    }
}

// ---------------- host launcher ----------------
extern "C" void kernel_launch(void* const* d_in, const int* in_sizes, int n_in,
                              void* d_out, int out_size)
{
    const float* x     = (const float*)d_in[0];
    // d_in[1] = mask (int32 causal tril) -- causal is hard-coded in the attention kernel
    const float* w_kvc = (const float*)d_in[2];
    const float* b_kvc = (const float*)d_in[3];
    const float* w_kvu = (const float*)d_in[4];
    const float* b_kvu = (const float*)d_in[5];
    const float* w_qc  = (const float*)d_in[6];
    const float* b_qc  = (const float*)d_in[7];
    const float* w_qu  = (const float*)d_in[8];
    const float* b_qu  = (const float*)d_in[9];
    const float* w_o   = (const float*)d_in[10];
    const float* b_o   = (const float*)d_in[11];
    float* out = (float*)d_out;

    float *lat, *kvup, *qc, *q, *ctx;
    cudaGetSymbolAddress((void**)&lat,  g_lat);
    cudaGetSymbolAddress((void**)&kvup, g_kvup);
    cudaGetSymbolAddress((void**)&qc,   g_qc);
    cudaGetSymbolAddress((void**)&q,    g_q);
    cudaGetSymbolAddress((void**)&ctx,  g_ctx);

    // 1. kv_latent = x @ w_kvc + b        [8192,128]   (BM=64,BN=128 -> 128 blocks)
    gemm_bias_kernel<4, 8><<<dim3(1, 128), 256>>>(x, w_kvc, b_kvc, lat, T_TOK, LATENT, DIM);
    // 2. kv_up = lat @ w_kvu + b          [8192,2048]
    gemm_bias_kernel<8, 8><<<dim3(2048 / 128, T_TOK / 128), 256>>>(lat, w_kvu, b_kvu, kvup, T_TOK, 2 * DIM, LATENT);
    // 3. q_c = x @ w_qc + b               [8192,256]
    gemm_bias_kernel<8, 8><<<dim3(QRANK / 128, T_TOK / 128), 256>>>(x, w_qc, b_qc, qc, T_TOK, QRANK, DIM);
    // 4. Q = q_c @ w_qu + b               [8192,1024]
    gemm_bias_kernel<8, 8><<<dim3(DIM / 128, T_TOK / 128), 256>>>(qc, w_qu, b_qu, q, T_TOK, DIM, QRANK);
    // 5. causal flash attention -> ctx
    const int SMEM = (4 * 64 * APAD + 3 * 64) * (int)sizeof(float);  // ~70.4 KB
    cudaFuncSetAttribute(flash_attn_kernel, cudaFuncAttributeMaxDynamicSharedMemorySize, SMEM);
    flash_attn_kernel<<<dim3(SEQ / 64, NHEADS, NBATCH), 256, SMEM>>>(q, kvup, ctx);
    // 6. out = ctx @ w_o + b              [8192,1024]
    gemm_bias_kernel<8, 8><<<dim3(DIM / 128, T_TOK / 128), 256>>>(ctx, w_o, b_o, out, T_TOK, DIM, DIM);
}

// round 2
// speedup vs baseline: 2.6815x; 2.6815x over previous
#include <cuda_runtime.h>
#include <cuda_bf16.h>
#include <cstdint>

// ---------------- problem constants ----------------
#define T_TOK   8192      // B*S
#define SEQ     2048
#define NBATCH  4
#define DIM     1024
#define NHEADS  16
#define HDIM    64
#define LATENT  128
#define QRANK   256

// ---------------- scratch (device globals; no allocation) ----------------
__device__ float g_lat [T_TOK * LATENT];        //  4 MB
__device__ float g_kvup[T_TOK * 2 * DIM];       // 64 MB  [K(1024) | V(1024)] per token
__device__ float g_qc  [T_TOK * QRANK];         //  8 MB
__device__ float g_q   [T_TOK * DIM];           // 32 MB
__device__ float g_ctx [T_TOK * DIM];           // 32 MB

// ---------------- tf32 helpers ----------------
__device__ __forceinline__ uint32_t f2t(float x) {
    uint32_t u;
    asm("cvt.rna.tf32.f32 %0, %1;" : "=r"(u) : "f"(x));
    return u;
}

// D += A(16x8) * B(8x8), tf32 inputs, f32 accumulate
__device__ __forceinline__ void mma8(float* c, const uint32_t* a, const uint32_t* b) {
    asm volatile(
        "mma.sync.aligned.m16n8k8.row.col.f32.tf32.tf32.f32 "
        "{%0,%1,%2,%3}, {%4,%5,%6,%7}, {%8,%9}, {%0,%1,%2,%3};"
        : "+f"(c[0]), "+f"(c[1]), "+f"(c[2]), "+f"(c[3])
        : "r"(a[0]), "r"(a[1]), "r"(a[2]), "r"(a[3]), "r"(b[0]), "r"(b[1]));
}

// ---------------- tf32 GEMM: C = A[M,K] @ W[K,N] + bias ----------------
// Block tile 128x128, BK=32. 256 threads = 8 warps (2 x 4). Warp tile 64x32.
__global__ __launch_bounds__(256, 2)
void gemm_tf32_kernel(const float* __restrict__ A, const float* __restrict__ W,
                      const float* __restrict__ bias, float* __restrict__ C,
                      int M, int N, int K)
{
    __shared__ uint32_t As[32][132];   // A^T tile: As[k][m]
    __shared__ uint32_t Bs[32][132];   // B tile:   Bs[k][n]

    const int tid  = threadIdx.x;
    const int lane = tid & 31;
    const int wid  = tid >> 5;
    const int wm   = (wid >> 2) * 64;   // warp m offset in block tile
    const int wn   = (wid & 3) * 32;    // warp n offset
    const int m0   = blockIdx.y * 128;
    const int n0   = blockIdx.x * 128;
    const int l4   = lane & 3;
    const int l2   = lane >> 2;

    float acc[4][4][4];
#pragma unroll
    for (int i = 0; i < 4; i++)
#pragma unroll
        for (int j = 0; j < 4; j++)
#pragma unroll
            for (int c = 0; c < 4; c++) acc[i][j][c] = 0.f;

    for (int k0 = 0; k0 < K; k0 += 32) {
        // A tile 128x32 -> As[k][m] (transposed, tf32)
#pragma unroll
        for (int v = 0; v < 4; v++) {
            int s = tid + v * 256;          // 0..1023 float4 slots
            int r = s >> 3, cv = s & 7;
            float4 a = *(const float4*)&A[(size_t)(m0 + r) * K + k0 + cv * 4];
            As[cv * 4 + 0][r] = f2t(a.x);
            As[cv * 4 + 1][r] = f2t(a.y);
            As[cv * 4 + 2][r] = f2t(a.z);
            As[cv * 4 + 3][r] = f2t(a.w);
        }
        // B tile 32x128 -> Bs[k][n] (tf32)
#pragma unroll
        for (int v = 0; v < 4; v++) {
            int s = tid + v * 256;
            int r = s >> 5, cv = s & 31;
            float4 b = *(const float4*)&W[(size_t)(k0 + r) * N + n0 + cv * 4];
            Bs[r][cv * 4 + 0] = f2t(b.x);
            Bs[r][cv * 4 + 1] = f2t(b.y);
            Bs[r][cv * 4 + 2] = f2t(b.z);
            Bs[r][cv * 4 + 3] = f2t(b.w);
        }
        __syncthreads();

#pragma unroll
        for (int kk = 0; kk < 4; kk++) {
            const int k = kk * 8;
            uint32_t af[4][4], bf[4][2];
#pragma unroll
            for (int im = 0; im < 4; im++) {
                int m = wm + im * 16 + l2;
                af[im][0] = As[k + l4][m];
                af[im][1] = As[k + l4][m + 8];
                af[im][2] = As[k + l4 + 4][m];
                af[im][3] = As[k + l4 + 4][m + 8];
            }
#pragma unroll
            for (int in = 0; in < 4; in++) {
                int n = wn + in * 8 + l2;
                bf[in][0] = Bs[k + l4][n];
                bf[in][1] = Bs[k + l4 + 4][n];
            }
#pragma unroll
            for (int im = 0; im < 4; im++)
#pragma unroll
                for (int in = 0; in < 4; in++)
                    mma8(acc[im][in], af[im], bf[in]);
        }
        __syncthreads();
    }

    // epilogue: add bias, store
#pragma unroll
    for (int im = 0; im < 4; im++) {
        int row = m0 + wm + im * 16 + l2;
#pragma unroll
        for (int in = 0; in < 4; in++) {
            int col = n0 + wn + in * 8 + 2 * l4;
            float b0 = bias[col], b1 = bias[col + 1];
            float2 v0 = make_float2(acc[im][in][0] + b0, acc[im][in][1] + b1);
            float2 v1 = make_float2(acc[im][in][2] + b0, acc[im][in][3] + b1);
            *(float2*)&C[(size_t)row * N + col]       = v0;
            *(float2*)&C[(size_t)(row + 8) * N + col] = v1;
        }
    }
}

// ---------------- causal flash attention, tf32 tensor cores, hd=64 ----------------
// grid = (S/64, H, B), block = 128 (4 warps). Warp w owns q rows [16w, 16w+16).
#define ASTR 68
__global__ __launch_bounds__(128)
void flash_tf32_kernel(const float* __restrict__ Q, const float* __restrict__ KV,
                       float* __restrict__ Ctx)
{
    extern __shared__ uint32_t sm[];
    uint32_t* Qs = sm;                 // [64][68] tf32, [q][d]  (Q pre-scaled)
    uint32_t* Ks = Qs + 64 * ASTR;     // [kv][d]
    uint32_t* Vs = Ks + 64 * ASTR;     // [kv][d]
    uint32_t* Ps = Vs + 64 * ASTR;     // [q][kv]

    const int qt = blockIdx.x;
    const int h  = blockIdx.y;
    const int b  = blockIdx.z;
    const int q0 = qt * 64;
    const int tid  = threadIdx.x;
    const int lane = tid & 31;
    const int w    = tid >> 5;
    const int l4   = lane & 3;
    const int l2   = lane >> 2;
    const int lrow0 = w * 16 + l2;     // local q row for c0,c1
    const int lrow1 = lrow0 + 8;       // local q row for c2,c3

    const size_t qbase = ((size_t)(b * SEQ + q0)) * DIM + h * HDIM;

    // load + scale Q
    for (int i = tid; i < 64 * 16; i += 128) {
        int r = i >> 4, cv = i & 15;
        float4 qv = *(const float4*)&Q[qbase + (size_t)r * DIM + cv * 4];
        Qs[r * ASTR + cv * 4 + 0] = f2t(qv.x * 0.125f);
        Qs[r * ASTR + cv * 4 + 1] = f2t(qv.y * 0.125f);
        Qs[r * ASTR + cv * 4 + 2] = f2t(qv.z * 0.125f);
        Qs[r * ASTR + cv * 4 + 3] = f2t(qv.w * 0.125f);
    }

    float m0r = -3.0e38f, m1r = -3.0e38f, l0 = 0.f, l1 = 0.f;
    float oacc[8][4];
#pragma unroll
    for (int n = 0; n < 8; n++)
#pragma unroll
        for (int c = 0; c < 4; c++) oacc[n][c] = 0.f;

    const int ntiles = qt + 1;
    for (int kt = 0; kt < ntiles; kt++) {
        __syncthreads();  // prev iter's Ks/Vs consumers done; also orders first-iter Qs
        const size_t kb = ((size_t)(b * SEQ + kt * 64)) * (2 * DIM) + h * HDIM;
        for (int i = tid; i < 64 * 16; i += 128) {
            int r = i >> 4, cv = i & 15;
            float4 kv4 = *(const float4*)&KV[kb + (size_t)r * (2 * DIM) + cv * 4];
            Ks[r * ASTR + cv * 4 + 0] = f2t(kv4.x);
            Ks[r * ASTR + cv * 4 + 1] = f2t(kv4.y);
            Ks[r * ASTR + cv * 4 + 2] = f2t(kv4.z);
            Ks[r * ASTR + cv * 4 + 3] = f2t(kv4.w);
            float4 vv = *(const float4*)&KV[kb + DIM + (size_t)r * (2 * DIM) + cv * 4];
            Vs[r * ASTR + cv * 4 + 0] = f2t(vv.x);
            Vs[r * ASTR + cv * 4 + 1] = f2t(vv.y);
            Vs[r * ASTR + cv * 4 + 2] = f2t(vv.z);
            Vs[r * ASTR + cv * 4 + 3] = f2t(vv.w);
        }
        __syncthreads();

        // S = Q K^T  (warp computes 16 x 64)
        float sacc[8][4];
#pragma unroll
        for (int n = 0; n < 8; n++)
#pragma unroll
            for (int c = 0; c < 4; c++) sacc[n][c] = 0.f;

#pragma unroll
        for (int kk = 0; kk < 8; kk++) {
            const int k = kk * 8;
            uint32_t a[4];
            a[0] = Qs[lrow0 * ASTR + k + l4];
            a[1] = Qs[lrow1 * ASTR + k + l4];
            a[2] = Qs[lrow0 * ASTR + k + l4 + 4];
            a[3] = Qs[lrow1 * ASTR + k + l4 + 4];
#pragma unroll
            for (int n = 0; n < 8; n++) {
                uint32_t bb[2];
                bb[0] = Ks[(n * 8 + l2) * ASTR + k + l4];
                bb[1] = Ks[(n * 8 + l2) * ASTR + k + l4 + 4];
                mma8(sacc[n], a, bb);
            }
        }

        // causal mask on diagonal tile (tile bases equal: local compare)
        if (kt == qt) {
#pragma unroll
            for (int n = 0; n < 8; n++) {
                int col = n * 8 + 2 * l4;
                if (col     > lrow0) sacc[n][0] = -1.0e30f;
                if (col + 1 > lrow0) sacc[n][1] = -1.0e30f;
                if (col     > lrow1) sacc[n][2] = -1.0e30f;
                if (col + 1 > lrow1) sacc[n][3] = -1.0e30f;
            }
        }

        // online softmax (rows lrow0 / lrow1; full row spread across the quad)
        float mx0 = -3.0e38f, mx1 = -3.0e38f;
#pragma unroll
        for (int n = 0; n < 8; n++) {
            mx0 = fmaxf(mx0, fmaxf(sacc[n][0], sacc[n][1]));
            mx1 = fmaxf(mx1, fmaxf(sacc[n][2], sacc[n][3]));
        }
        mx0 = fmaxf(mx0, __shfl_xor_sync(0xffffffffu, mx0, 1));
        mx0 = fmaxf(mx0, __shfl_xor_sync(0xffffffffu, mx0, 2));
        mx1 = fmaxf(mx1, __shfl_xor_sync(0xffffffffu, mx1, 1));
        mx1 = fmaxf(mx1, __shfl_xor_sync(0xffffffffu, mx1, 2));

        float mn0 = fmaxf(m0r, mx0), mn1 = fmaxf(m1r, mx1);
        float al0 = __expf(m0r - mn0), al1 = __expf(m1r - mn1);
        float s0 = 0.f, s1 = 0.f;
#pragma unroll
        for (int n = 0; n < 8; n++) {
            float p0 = __expf(sacc[n][0] - mn0);
            float p1 = __expf(sacc[n][1] - mn0);
            float p2 = __expf(sacc[n][2] - mn1);
            float p3 = __expf(sacc[n][3] - mn1);
            sacc[n][0] = p0; sacc[n][1] = p1; sacc[n][2] = p2; sacc[n][3] = p3;
            s0 += p0 + p1;
            s1 += p2 + p3;
        }
        s0 += __shfl_xor_sync(0xffffffffu, s0, 1);
        s0 += __shfl_xor_sync(0xffffffffu, s0, 2);
        s1 += __shfl_xor_sync(0xffffffffu, s1, 1);
        s1 += __shfl_xor_sync(0xffffffffu, s1, 2);
        l0 = l0 * al0 + s0;
        l1 = l1 * al1 + s1;
        m0r = mn0; m1r = mn1;

#pragma unroll
        for (int n = 0; n < 8; n++) {
            oacc[n][0] *= al0; oacc[n][1] *= al0;
            oacc[n][2] *= al1; oacc[n][3] *= al1;
        }

        // write P (warp-private rows) as tf32
#pragma unroll
        for (int n = 0; n < 8; n++) {
            int col = n * 8 + 2 * l4;
            Ps[lrow0 * ASTR + col]     = f2t(sacc[n][0]);
            Ps[lrow0 * ASTR + col + 1] = f2t(sacc[n][1]);
            Ps[lrow1 * ASTR + col]     = f2t(sacc[n][2]);
            Ps[lrow1 * ASTR + col + 1] = f2t(sacc[n][3]);
        }
        __syncwarp();

        // O += P @ V   (k = kv, n = d)
#pragma unroll
        for (int kk = 0; kk < 8; kk++) {
            const int k = kk * 8;
            uint32_t a[4];
            a[0] = Ps[lrow0 * ASTR + k + l4];
            a[1] = Ps[lrow1 * ASTR + k + l4];
            a[2] = Ps[lrow0 * ASTR + k + l4 + 4];
            a[3] = Ps[lrow1 * ASTR + k + l4 + 4];
#pragma unroll
            for (int n = 0; n < 8; n++) {
                uint32_t bb[2];
                bb[0] = Vs[(k + l4) * ASTR + n * 8 + l2];
                bb[1] = Vs[(k + l4 + 4) * ASTR + n * 8 + l2];
                mma8(oacc[n], a, bb);
            }
        }
        __syncwarp();  // PV reads of Ps done before any later overwrite
    }

    // epilogue: normalize and write ctx
    const float inv0 = 1.f / l0, inv1 = 1.f / l1;
    const size_t ob0 = ((size_t)(b * SEQ + q0 + lrow0)) * DIM + h * HDIM;
    const size_t ob1 = ((size_t)(b * SEQ + q0 + lrow1)) * DIM + h * HDIM;
#pragma unroll
    for (int n = 0; n < 8; n++) {
        int col = n * 8 + 2 * l4;
        *(float2*)&Ctx[ob0 + col] = make_float2(oacc[n][0] * inv0, oacc[n][1] * inv0);
        *(float2*)&Ctx[ob1 + col] = make_float2(oacc[n][2] * inv1, oacc[n][3] * inv1);
    }
}

// ---------------- host launcher ----------------
extern "C" void kernel_launch(void* const* d_in, const int* in_sizes, int n_in,
                              void* d_out, int out_size)
{
    const float* x     = (const float*)d_in[0];
    // d_in[1] = mask (causal, hard-coded)
    const float* w_kvc = (const float*)d_in[2];
    const float* b_kvc = (const float*)d_in[3];
    const float* w_kvu = (const float*)d_in[4];
    const float* b_kvu = (const float*)d_in[5];
    const float* w_qc  = (const float*)d_in[6];
    const float* b_qc  = (const float*)d_in[7];
    const float* w_qu  = (const float*)d_in[8];
    const float* b_qu  = (const float*)d_in[9];
    const float* w_o   = (const float*)d_in[10];
    const float* b_o   = (const float*)d_in[11];
    float* out = (float*)d_out;

    float *lat, *kvup, *qc, *q, *ctx;
    cudaGetSymbolAddress((void**)&lat,  g_lat);
    cudaGetSymbolAddress((void**)&kvup, g_kvup);
    cudaGetSymbolAddress((void**)&qc,   g_qc);
    cudaGetSymbolAddress((void**)&q,    g_q);
    cudaGetSymbolAddress((void**)&ctx,  g_ctx);

    // 1. kv_latent = x @ w_kvc + b        [8192,128]
    gemm_tf32_kernel<<<dim3(LATENT / 128, T_TOK / 128), 256>>>(x, w_kvc, b_kvc, lat, T_TOK, LATENT, DIM);
    // 2. kv_up = lat @ w_kvu + b          [8192,2048]
    gemm_tf32_kernel<<<dim3(2 * DIM / 128, T_TOK / 128), 256>>>(lat, w_kvu, b_kvu, kvup, T_TOK, 2 * DIM, LATENT);
    // 3. q_c = x @ w_qc + b               [8192,256]
    gemm_tf32_kernel<<<dim3(QRANK / 128, T_TOK / 128), 256>>>(x, w_qc, b_qc, qc, T_TOK, QRANK, DIM);
    // 4. Q = q_c @ w_qu + b               [8192,1024]
    gemm_tf32_kernel<<<dim3(DIM / 128, T_TOK / 128), 256>>>(qc, w_qu, b_qu, q, T_TOK, DIM, QRANK);
    // 5. causal flash attention -> ctx
    const int SMEM = 4 * 64 * ASTR * (int)sizeof(uint32_t);  // ~69.6 KB
    cudaFuncSetAttribute(flash_tf32_kernel, cudaFuncAttributeMaxDynamicSharedMemorySize, SMEM);
    flash_tf32_kernel<<<dim3(SEQ / 64, NHEADS, NBATCH), 128, SMEM>>>(q, kvup, ctx);
    // 6. out = ctx @ w_o + b              [8192,1024]
    gemm_tf32_kernel<<<dim3(DIM / 128, T_TOK / 128), 256>>>(ctx, w_o, b_o, out, T_TOK, DIM, DIM);
}

// round 3
// speedup vs baseline: 2.9826x; 1.1123x over previous
#include <cuda_runtime.h>
#include <cuda_bf16.h>
#include <cstdint>

// ---------------- problem constants ----------------
#define T_TOK   8192      // B*S
#define SEQ     2048
#define NBATCH  4
#define DIM     1024
#define NHEADS  16
#define HDIM    64
#define LATENT  128
#define QRANK   256

#define QSCALE  0.18033688011112042f   // (1/sqrt(64)) * log2(e)

// ---------------- scratch (device globals; no allocation) ----------------
__device__ float g_lat [T_TOK * LATENT];        //  4 MB
__device__ float g_kvup[T_TOK * 2 * DIM];       // 64 MB  tf32 bit patterns [K | V]
__device__ float g_qc  [T_TOK * QRANK];         //  8 MB
__device__ float g_q   [T_TOK * DIM];           // 32 MB  tf32 bit patterns, pre-scaled
__device__ float g_ctx [T_TOK * DIM];           // 32 MB

// ---------------- helpers ----------------
__device__ __forceinline__ uint32_t f2t(float x) {
    uint32_t u;
    asm("cvt.rna.tf32.f32 %0, %1;" : "=r"(u) : "f"(x));
    return u;
}
__device__ __forceinline__ float ex2(float x) {
    float r;
    asm("ex2.approx.f32 %0, %1;" : "=f"(r) : "f"(x));
    return r;
}
// D += A(16x8) * B(8x8), tf32 inputs, f32 accumulate
__device__ __forceinline__ void mma8(float* c, const uint32_t* a, const uint32_t* b) {
    asm volatile(
        "mma.sync.aligned.m16n8k8.row.col.f32.tf32.tf32.f32 "
        "{%0,%1,%2,%3}, {%4,%5,%6,%7}, {%8,%9}, {%0,%1,%2,%3};"
        : "+f"(c[0]), "+f"(c[1]), "+f"(c[2]), "+f"(c[3])
        : "r"(a[0]), "r"(a[1]), "r"(a[2]), "r"(a[3]), "r"(b[0]), "r"(b[1]));
}

// ---------------- tf32 GEMM: C = A[M,K] @ W[K,N] + bias ----------------
// MODE 0: store fp32.  MODE 1: store tf32 bit pattern of scale*(acc+bias).
template<int MODE>
__global__ __launch_bounds__(256, 2)
void gemm_tf32_kernel(const float* __restrict__ A, const float* __restrict__ W,
                      const float* __restrict__ bias, float* __restrict__ C,
                      int M, int N, int K, float scale)
{
    __shared__ uint32_t As[32][132];   // A^T tile: As[k][m]
    __shared__ uint32_t Bs[32][132];   // B tile:   Bs[k][n]

    const int tid  = threadIdx.x;
    const int lane = tid & 31;
    const int wid  = tid >> 5;
    const int wm   = (wid >> 2) * 64;
    const int wn   = (wid & 3) * 32;
    const int m0   = blockIdx.y * 128;
    const int n0   = blockIdx.x * 128;
    const int l4   = lane & 3;
    const int l2   = lane >> 2;

    float acc[4][4][4];
#pragma unroll
    for (int i = 0; i < 4; i++)
#pragma unroll
        for (int j = 0; j < 4; j++)
#pragma unroll
            for (int c = 0; c < 4; c++) acc[i][j][c] = 0.f;

    for (int k0 = 0; k0 < K; k0 += 32) {
#pragma unroll
        for (int v = 0; v < 4; v++) {
            int s = tid + v * 256;
            int r = s >> 3, cv = s & 7;
            float4 a = *(const float4*)&A[(size_t)(m0 + r) * K + k0 + cv * 4];
            As[cv * 4 + 0][r] = f2t(a.x);
            As[cv * 4 + 1][r] = f2t(a.y);
            As[cv * 4 + 2][r] = f2t(a.z);
            As[cv * 4 + 3][r] = f2t(a.w);
        }
#pragma unroll
        for (int v = 0; v < 4; v++) {
            int s = tid + v * 256;
            int r = s >> 5, cv = s & 31;
            float4 b = *(const float4*)&W[(size_t)(k0 + r) * N + n0 + cv * 4];
            Bs[r][cv * 4 + 0] = f2t(b.x);
            Bs[r][cv * 4 + 1] = f2t(b.y);
            Bs[r][cv * 4 + 2] = f2t(b.z);
            Bs[r][cv * 4 + 3] = f2t(b.w);
        }
        __syncthreads();

#pragma unroll
        for (int kk = 0; kk < 4; kk++) {
            const int k = kk * 8;
            uint32_t af[4][4], bf[4][2];
#pragma unroll
            for (int im = 0; im < 4; im++) {
                int m = wm + im * 16 + l2;
                af[im][0] = As[k + l4][m];
                af[im][1] = As[k + l4][m + 8];
                af[im][2] = As[k + l4 + 4][m];
                af[im][3] = As[k + l4 + 4][m + 8];
            }
#pragma unroll
            for (int in = 0; in < 4; in++) {
                int n = wn + in * 8 + l2;
                bf[in][0] = Bs[k + l4][n];
                bf[in][1] = Bs[k + l4 + 4][n];
            }
#pragma unroll
            for (int im = 0; im < 4; im++)
#pragma unroll
                for (int in = 0; in < 4; in++)
                    mma8(acc[im][in], af[im], bf[in]);
        }
        __syncthreads();
    }

#pragma unroll
    for (int im = 0; im < 4; im++) {
        int row = m0 + wm + im * 16 + l2;
#pragma unroll
        for (int in = 0; in < 4; in++) {
            int col = n0 + wn + in * 8 + 2 * l4;
            float b0 = bias[col], b1 = bias[col + 1];
            float2 v0, v1;
            if (MODE == 0) {
                v0 = make_float2(acc[im][in][0] + b0, acc[im][in][1] + b1);
                v1 = make_float2(acc[im][in][2] + b0, acc[im][in][3] + b1);
            } else {
                v0 = make_float2(__uint_as_float(f2t(scale * (acc[im][in][0] + b0))),
                                 __uint_as_float(f2t(scale * (acc[im][in][1] + b1))));
                v1 = make_float2(__uint_as_float(f2t(scale * (acc[im][in][2] + b0))),
                                 __uint_as_float(f2t(scale * (acc[im][in][3] + b1))));
            }
            *(float2*)&C[(size_t)row * N + col]       = v0;
            *(float2*)&C[(size_t)(row + 8) * N + col] = v1;
        }
    }
}

// ---------------- causal flash attention, tf32 tensor cores, hd=64 ----------------
// BQ=128 q rows/CTA, 8 warps; kv tile 64. Operands arrive as tf32 bit patterns.
// Smem: Qs/Ks/Ps in pair-permuted column layout (fragment = one LDS.64), Vs natural.
#define BQ   128
#define SKT  72
__global__ __launch_bounds__(256, 2)
void flash_tf32_kernel(const uint32_t* __restrict__ Q, const uint32_t* __restrict__ KV,
                       float* __restrict__ Ctx)
{
    extern __shared__ uint32_t sm[];
    uint32_t* Qs = sm;                     // [BQ][SKT] permuted
    uint32_t* Ks = Qs + BQ * SKT;          // [64][SKT] permuted
    uint32_t* Vs = Ks + 64 * SKT;          // [64][SKT] natural
    uint32_t* Ps = Vs + 64 * SKT;          // [BQ][SKT] permuted

    const int qt = blockIdx.x;
    const int h  = blockIdx.y;
    const int b  = blockIdx.z;
    const int q0 = qt * BQ;
    const int tid  = threadIdx.x;
    const int lane = tid & 31;
    const int w    = tid >> 5;
    const int l4   = lane & 3;
    const int l2   = lane >> 2;
    const int lrow0 = w * 16 + l2;
    const int lrow1 = lrow0 + 8;

    // ---- load Q (pre-scaled tf32 patterns) into permuted smem ----
    const size_t qbase = ((size_t)(b * SEQ + q0)) * DIM + h * HDIM;
#pragma unroll
    for (int v = 0; v < 8; v++) {
        int i = tid + v * 256;
        int r = i >> 4, cv = i & 15;
        uint4 qv = *(const uint4*)(Q + qbase + (size_t)r * DIM + cv * 4);
        uint32_t* dst = Qs + r * SKT + 8 * (cv >> 1) + (cv & 1);
        dst[0] = qv.x; dst[2] = qv.y; dst[4] = qv.z; dst[6] = qv.w;
    }

    float mr0 = -1.0e30f, mr1 = -1.0e30f, lr0 = 0.f, lr1 = 0.f;
    float oacc[8][4];
#pragma unroll
    for (int n = 0; n < 8; n++)
#pragma unroll
        for (int c = 0; c < 4; c++) oacc[n][c] = 0.f;

    const int ntiles = 2 * qt + 2;
    uint4 kreg[4], vreg[4];

    // prefetch tile 0
    {
        const size_t kb = ((size_t)(b * SEQ)) * (2 * DIM) + h * HDIM;
#pragma unroll
        for (int v = 0; v < 4; v++) {
            int i = tid + v * 256;
            int r = i >> 4, cv = i & 15;
            kreg[v] = *(const uint4*)(KV + kb + (size_t)r * (2 * DIM) + cv * 4);
            vreg[v] = *(const uint4*)(KV + kb + DIM + (size_t)r * (2 * DIM) + cv * 4);
        }
    }

    for (int kt = 0; kt < ntiles; kt++) {
        __syncthreads();   // prior tile's smem consumers done (also covers Q store, iter 0)
        // store prefetched K (permuted) / V (natural)
#pragma unroll
        for (int v = 0; v < 4; v++) {
            int i = tid + v * 256;
            int r = i >> 4, cv = i & 15;
            uint32_t* kd = Ks + r * SKT + 8 * (cv >> 1) + (cv & 1);
            kd[0] = kreg[v].x; kd[2] = kreg[v].y; kd[4] = kreg[v].z; kd[6] = kreg[v].w;
            *(uint4*)(Vs + r * SKT + cv * 4) = vreg[v];
        }
        __syncthreads();

        // prefetch next tile (overlaps with compute below)
        if (kt + 1 < ntiles) {
            const size_t kb = ((size_t)(b * SEQ + (kt + 1) * 64)) * (2 * DIM) + h * HDIM;
#pragma unroll
            for (int v = 0; v < 4; v++) {
                int i = tid + v * 256;
                int r = i >> 4, cv = i & 15;
                kreg[v] = *(const uint4*)(KV + kb + (size_t)r * (2 * DIM) + cv * 4);
                vreg[v] = *(const uint4*)(KV + kb + DIM + (size_t)r * (2 * DIM) + cv * 4);
            }
        }

        const int k0 = kt * 64;
        const bool active = (k0 <= q0 + w * 16 + 15);   // tile intersects this warp's rows
        if (active) {
            // ---- S = Q K^T (warp: 16 x 64) ----
            float sacc[8][4];
#pragma unroll
            for (int n = 0; n < 8; n++)
#pragma unroll
                for (int c = 0; c < 4; c++) sacc[n][c] = 0.f;

#pragma unroll
            for (int kk = 0; kk < 8; kk++) {
                uint2 a01 = *(const uint2*)(Qs + lrow0 * SKT + kk * 8 + 2 * l4);
                uint2 a23 = *(const uint2*)(Qs + lrow1 * SKT + kk * 8 + 2 * l4);
                uint32_t a[4] = {a01.x, a23.x, a01.y, a23.y};
#pragma unroll
                for (int n = 0; n < 8; n++) {
                    uint2 bv = *(const uint2*)(Ks + (n * 8 + l2) * SKT + kk * 8 + 2 * l4);
                    uint32_t bb[2] = {bv.x, bv.y};
                    mma8(sacc[n], a, bb);
                }
            }

            // ---- causal mask (only tiles crossing this warp's diagonal) ----
            if (k0 + 63 > q0 + w * 16) {
                const int g0 = q0 + lrow0, g1 = q0 + lrow1;
#pragma unroll
                for (int n = 0; n < 8; n++) {
                    int cg = k0 + n * 8 + 2 * l4;
                    if (cg     > g0) sacc[n][0] = -1.0e30f;
                    if (cg + 1 > g0) sacc[n][1] = -1.0e30f;
                    if (cg     > g1) sacc[n][2] = -1.0e30f;
                    if (cg + 1 > g1) sacc[n][3] = -1.0e30f;
                }
            }

            // ---- online softmax (log2 domain; Q was pre-scaled by log2e/8) ----
            float mx0 = -1.0e30f, mx1 = -1.0e30f;
#pragma unroll
            for (int n = 0; n < 8; n++) {
                mx0 = fmaxf(mx0, fmaxf(sacc[n][0], sacc[n][1]));
                mx1 = fmaxf(mx1, fmaxf(sacc[n][2], sacc[n][3]));
            }
            mx0 = fmaxf(mx0, __shfl_xor_sync(0xffffffffu, mx0, 1));
            mx0 = fmaxf(mx0, __shfl_xor_sync(0xffffffffu, mx0, 2));
            mx1 = fmaxf(mx1, __shfl_xor_sync(0xffffffffu, mx1, 1));
            mx1 = fmaxf(mx1, __shfl_xor_sync(0xffffffffu, mx1, 2));

            float mn0 = fmaxf(mr0, mx0), mn1 = fmaxf(mr1, mx1);
            float al0 = ex2(mr0 - mn0),  al1 = ex2(mr1 - mn1);
            float s0 = 0.f, s1 = 0.f;
#pragma unroll
            for (int n = 0; n < 8; n++) {
                float p0 = ex2(sacc[n][0] - mn0);
                float p1 = ex2(sacc[n][1] - mn0);
                float p2 = ex2(sacc[n][2] - mn1);
                float p3 = ex2(sacc[n][3] - mn1);
                sacc[n][0] = p0; sacc[n][1] = p1; sacc[n][2] = p2; sacc[n][3] = p3;
                s0 += p0 + p1;
                s1 += p2 + p3;
            }
            s0 += __shfl_xor_sync(0xffffffffu, s0, 1);
            s0 += __shfl_xor_sync(0xffffffffu, s0, 2);
            s1 += __shfl_xor_sync(0xffffffffu, s1, 1);
            s1 += __shfl_xor_sync(0xffffffffu, s1, 2);
            lr0 = lr0 * al0 + s0;
            lr1 = lr1 * al1 + s1;
            mr0 = mn0; mr1 = mn1;

#pragma unroll
            for (int n = 0; n < 8; n++) {
                oacc[n][0] *= al0; oacc[n][1] *= al0;
                oacc[n][2] *= al1; oacc[n][3] *= al1;
            }

            // ---- write P into permuted layout (warp-private rows) ----
            const int p0off = (l4 < 2) ? 4 * l4 : 4 * l4 - 7;
#pragma unroll
            for (int n = 0; n < 8; n++) {
                uint32_t* r0p = Ps + lrow0 * SKT + n * 8 + p0off;
                uint32_t* r1p = Ps + lrow1 * SKT + n * 8 + p0off;
                r0p[0] = f2t(sacc[n][0]); r0p[2] = f2t(sacc[n][1]);
                r1p[0] = f2t(sacc[n][2]); r1p[2] = f2t(sacc[n][3]);
            }
            __syncwarp();

            // ---- O += P @ V ----
#pragma unroll
            for (int kk = 0; kk < 8; kk++) {
                uint2 a01 = *(const uint2*)(Ps + lrow0 * SKT + kk * 8 + 2 * l4);
                uint2 a23 = *(const uint2*)(Ps + lrow1 * SKT + kk * 8 + 2 * l4);
                uint32_t a[4] = {a01.x, a23.x, a01.y, a23.y};
                const uint32_t* vb0 = Vs + (kk * 8 + l4) * SKT + l2;
                const uint32_t* vb1 = vb0 + 4 * SKT;
#pragma unroll
                for (int n = 0; n < 8; n++) {
                    uint32_t bb[2] = {vb0[n * 8], vb1[n * 8]};
                    mma8(oacc[n], a, bb);
                }
            }
        }
    }

    // ---- epilogue ----
    const float inv0 = 1.f / lr0, inv1 = 1.f / lr1;
    const size_t ob0 = ((size_t)(b * SEQ + q0 + lrow0)) * DIM + h * HDIM;
    const size_t ob1 = ((size_t)(b * SEQ + q0 + lrow1)) * DIM + h * HDIM;
#pragma unroll
    for (int n = 0; n < 8; n++) {
        int col = n * 8 + 2 * l4;
        *(float2*)&Ctx[ob0 + col] = make_float2(oacc[n][0] * inv0, oacc[n][1] * inv0);
        *(float2*)&Ctx[ob1 + col] = make_float2(oacc[n][2] * inv1, oacc[n][3] * inv1);
    }
}

// ---------------- host launcher ----------------
extern "C" void kernel_launch(void* const* d_in, const int* in_sizes, int n_in,
                              void* d_out, int out_size)
{
    const float* x     = (const float*)d_in[0];
    // d_in[1] = mask (causal, hard-coded)
    const float* w_kvc = (const float*)d_in[2];
    const float* b_kvc = (const float*)d_in[3];
    const float* w_kvu = (const float*)d_in[4];
    const float* b_kvu = (const float*)d_in[5];
    const float* w_qc  = (const float*)d_in[6];
    const float* b_qc  = (const float*)d_in[7];
    const float* w_qu  = (const float*)d_in[8];
    const float* b_qu  = (const float*)d_in[9];
    const float* w_o   = (const float*)d_in[10];
    const float* b_o   = (const float*)d_in[11];
    float* out = (float*)d_out;

    float *lat, *kvup, *qc, *q, *ctx;
    cudaGetSymbolAddress((void**)&lat,  g_lat);
    cudaGetSymbolAddress((void**)&kvup, g_kvup);
    cudaGetSymbolAddress((void**)&qc,   g_qc);
    cudaGetSymbolAddress((void**)&q,    g_q);
    cudaGetSymbolAddress((void**)&ctx,  g_ctx);

    // 1. kv_latent = x @ w_kvc + b            [8192,128]  fp32
    gemm_tf32_kernel<0><<<dim3(LATENT / 128, T_TOK / 128), 256>>>(x, w_kvc, b_kvc, lat, T_TOK, LATENT, DIM, 1.f);
    // 2. kv_up = lat @ w_kvu + b              [8192,2048] -> tf32 patterns
    gemm_tf32_kernel<1><<<dim3(2 * DIM / 128, T_TOK / 128), 256>>>(lat, w_kvu, b_kvu, kvup, T_TOK, 2 * DIM, LATENT, 1.f);
    // 3. q_c = x @ w_qc + b                   [8192,256]  fp32
    gemm_tf32_kernel<0><<<dim3(QRANK / 128, T_TOK / 128), 256>>>(x, w_qc, b_qc, qc, T_TOK, QRANK, DIM, 1.f);
    // 4. Q = q_c @ w_qu + b                   [8192,1024] -> tf32 patterns * (log2e/8)
    gemm_tf32_kernel<1><<<dim3(DIM / 128, T_TOK / 128), 256>>>(qc, w_qu, b_qu, q, T_TOK, DIM, QRANK, QSCALE);
    // 5. causal flash attention -> ctx (fp32)
    const int SMEM = (2 * BQ + 2 * 64) * SKT * (int)sizeof(uint32_t);   // 110.6 KB
    cudaFuncSetAttribute(flash_tf32_kernel, cudaFuncAttributeMaxDynamicSharedMemorySize, SMEM);
    flash_tf32_kernel<<<dim3(SEQ / BQ, NHEADS, NBATCH), 256, SMEM>>>(
        (const uint32_t*)q, (const uint32_t*)kvup, ctx);
    // 6. out = ctx @ w_o + b                  [8192,1024] fp32
    gemm_tf32_kernel<0><<<dim3(DIM / 128, T_TOK / 128), 256>>>(ctx, w_o, b_o, out, T_TOK, DIM, DIM, 1.f);
}

// round 5
// speedup vs baseline: 3.0536x; 1.0238x over previous
#include <cuda_runtime.h>
#include <cuda_bf16.h>
#include <cstdint>

// ---------------- problem constants ----------------
#define T_TOK   8192      // B*S
#define SEQ     2048
#define NBATCH  4
#define DIM     1024
#define NHEADS  16
#define HDIM    64
#define LATENT  128
#define QRANK   256

#define QSCALE  0.18033688011112042f   // (1/sqrt(64)) * log2(e)

// ---------------- scratch (device globals; no allocation) ----------------
__device__ float g_lat [T_TOK * LATENT];        // tf32 patterns
__device__ float g_kvup[T_TOK * 2 * DIM];       // tf32 patterns [K | V]
__device__ float g_qc  [T_TOK * QRANK];         // tf32 patterns
__device__ float g_q   [T_TOK * DIM];           // tf32 patterns, pre-scaled by QSCALE
__device__ float g_ctx [T_TOK * DIM];           // tf32 patterns
__device__ uint32_t g_xt  [T_TOK * DIM];        // x as tf32
__device__ uint32_t g_wkvc[DIM * LATENT];
__device__ uint32_t g_wqc [DIM * QRANK];
__device__ uint32_t g_wkvu[LATENT * 2 * DIM];
__device__ uint32_t g_wqu [QRANK * DIM];
__device__ uint32_t g_wo  [DIM * DIM];

// ---------------- helpers ----------------
__device__ __forceinline__ uint32_t f2t(float x) {
    uint32_t u;
    asm("cvt.rna.tf32.f32 %0, %1;" : "=r"(u) : "f"(x));
    return u;
}
__device__ __forceinline__ float ex2(float x) {
    float r;
    asm("ex2.approx.f32 %0, %1;" : "=f"(r) : "f"(x));
    return r;
}
__device__ __forceinline__ void mma8(float* c, const uint32_t* a, const uint32_t* b) {
    asm volatile(
        "mma.sync.aligned.m16n8k8.row.col.f32.tf32.tf32.f32 "
        "{%0,%1,%2,%3}, {%4,%5,%6,%7}, {%8,%9}, {%0,%1,%2,%3};"
        : "+f"(c[0]), "+f"(c[1]), "+f"(c[2]), "+f"(c[3])
        : "r"(a[0]), "r"(a[1]), "r"(a[2]), "r"(a[3]), "r"(b[0]), "r"(b[1]));
}

// ---------------- fp32 -> tf32 convert ----------------
__global__ void cvt_tf32_kernel(const float4* __restrict__ src, uint4* __restrict__ dst, int n4)
{
    int i = blockIdx.x * 256 + threadIdx.x;
    if (i < n4) {
        float4 v = src[i];
        uint4 u;
        u.x = f2t(v.x); u.y = f2t(v.y); u.z = f2t(v.z); u.w = f2t(v.w);
        dst[i] = u;
    }
}

// ---------------- GEMM body: C = A[M,K](tf32) @ W[K,N](tf32) + bias ----------------
// Round-3-proven smem layout (As[k][m] transposed, Bs[k][n], stride 132), BK=32,
// block tile 128x128, 256 threads, warp tile 64x32. Register-prefetch double buffer.
// MODE 0: store fp32.  MODE 1: store tf32 bit pattern of scale*(acc+bias).
#define GSTR  132
#define GEMM_SMEM (2 * 32 * GSTR * 4)   // 33792 B (< 48KB, no attr needed)

template<int MODE>
__device__ __forceinline__ void gemm_body(
    const uint32_t* __restrict__ A, const uint32_t* __restrict__ W,
    const float* __restrict__ bias, float* __restrict__ C,
    int N, int K, int m0, int n0, float scale, uint32_t* As, uint32_t* Bs)
{
    const int tid  = threadIdx.x;
    const int lane = tid & 31;
    const int wid  = tid >> 5;
    const int wm   = (wid >> 2) * 64;
    const int wn   = (wid & 3) * 32;
    const int l4   = lane & 3;
    const int l2   = lane >> 2;

    const int ar0 = tid >> 3;          // A row base (+32 per v)
    const int ca  = (tid & 7) * 4;     // A col base
    const int br0 = tid >> 5;          // B row base (+8 per v)
    const int cb  = (tid & 31) * 4;    // B col base

    float acc[4][4][4];
#pragma unroll
    for (int i = 0; i < 4; i++)
#pragma unroll
        for (int j = 0; j < 4; j++)
#pragma unroll
            for (int c = 0; c < 4; c++) acc[i][j][c] = 0.f;

    const int nk = K >> 5;
    uint4 areg[4], breg[4];

    auto gload = [&](int k0) {
#pragma unroll
        for (int v = 0; v < 4; v++) {
            areg[v] = *(const uint4*)(A + (size_t)(m0 + ar0 + v * 32) * K + k0 + ca);
            breg[v] = *(const uint4*)(W + (size_t)(k0 + br0 + v * 8) * N + n0 + cb);
        }
    };

    gload(0);
    for (int kt = 0; kt < nk; kt++) {
        __syncthreads();   // previous compute done reading smem
#pragma unroll
        for (int v = 0; v < 4; v++) {
            int r = ar0 + v * 32;
            As[(ca + 0) * GSTR + r] = areg[v].x;
            As[(ca + 1) * GSTR + r] = areg[v].y;
            As[(ca + 2) * GSTR + r] = areg[v].z;
            As[(ca + 3) * GSTR + r] = areg[v].w;
            *(uint4*)(Bs + (br0 + v * 8) * GSTR + cb) = breg[v];
        }
        __syncthreads();

        if (kt + 1 < nk) gload((kt + 1) << 5);   // overlap LDG with MMAs

#pragma unroll
        for (int kk = 0; kk < 4; kk++) {
            const int k = kk * 8;
            uint32_t af[4][4], bf[4][2];
#pragma unroll
            for (int im = 0; im < 4; im++) {
                int m = wm + im * 16 + l2;
                af[im][0] = As[(k + l4) * GSTR + m];
                af[im][1] = As[(k + l4) * GSTR + m + 8];
                af[im][2] = As[(k + l4 + 4) * GSTR + m];
                af[im][3] = As[(k + l4 + 4) * GSTR + m + 8];
            }
#pragma unroll
            for (int in = 0; in < 4; in++) {
                int n = wn + in * 8 + l2;
                bf[in][0] = Bs[(k + l4) * GSTR + n];
                bf[in][1] = Bs[(k + l4 + 4) * GSTR + n];
            }
#pragma unroll
            for (int im = 0; im < 4; im++)
#pragma unroll
                for (int in = 0; in < 4; in++)
                    mma8(acc[im][in], af[im], bf[in]);
        }
    }

#pragma unroll
    for (int im = 0; im < 4; im++) {
        int row = m0 + wm + im * 16 + l2;
#pragma unroll
        for (int in = 0; in < 4; in++) {
            int col = n0 + wn + in * 8 + 2 * l4;
            float b0 = bias[col], b1 = bias[col + 1];
            float2 v0, v1;
            if (MODE == 0) {
                v0 = make_float2(acc[im][in][0] + b0, acc[im][in][1] + b1);
                v1 = make_float2(acc[im][in][2] + b0, acc[im][in][3] + b1);
            } else {
                v0 = make_float2(__uint_as_float(f2t(scale * (acc[im][in][0] + b0))),
                                 __uint_as_float(f2t(scale * (acc[im][in][1] + b1))));
                v1 = make_float2(__uint_as_float(f2t(scale * (acc[im][in][2] + b0))),
                                 __uint_as_float(f2t(scale * (acc[im][in][3] + b1))));
            }
            *(float2*)&C[(size_t)row * N + col]       = v0;
            *(float2*)&C[(size_t)(row + 8) * N + col] = v1;
        }
    }
}

template<int MODE>
__global__ __launch_bounds__(256, 2)
void gemm_tt_kernel(const uint32_t* __restrict__ A, const uint32_t* __restrict__ W,
                    const float* __restrict__ bias, float* __restrict__ C,
                    int N, int K, float scale)
{
    extern __shared__ uint32_t smg[];
    gemm_body<MODE>(A, W, bias, C, N, K, blockIdx.y * 128, blockIdx.x * 128, scale,
                    smg, smg + 32 * GSTR);
}

// fused kv_latent (N=128) + q_c (N=256): grid.x = 3 column tiles, K=1024
__global__ __launch_bounds__(256, 2)
void fused_latqc_kernel(const uint32_t* __restrict__ X,
                        const uint32_t* __restrict__ Wkvc, const float* __restrict__ bkvc, float* __restrict__ lat,
                        const uint32_t* __restrict__ Wqc,  const float* __restrict__ bqc,  float* __restrict__ qc)
{
    extern __shared__ uint32_t smg[];
    const int bx = blockIdx.x;
    if (bx == 0)
        gemm_body<1>(X, Wkvc, bkvc, lat, LATENT, DIM, blockIdx.y * 128, 0, 1.f,
                     smg, smg + 32 * GSTR);
    else
        gemm_body<1>(X, Wqc, bqc, qc, QRANK, DIM, blockIdx.y * 128, (bx - 1) * 128, 1.f,
                     smg, smg + 32 * GSTR);
}

// ---------------- causal flash attention, tf32, hd=64 (round-3 proven) ----------------
// BQ=128 q rows/CTA, 8 warps; kv tile 64, register-prefetch double buffer.
#define BQ   128
#define SKT  72
#define FL_SMEM ((2 * BQ + 2 * 64) * SKT * 4)   // 110592 B

__global__ __launch_bounds__(256, 2)
void flash_tf32_kernel(const uint32_t* __restrict__ Q, const uint32_t* __restrict__ KV,
                       float* __restrict__ Ctx)
{
    extern __shared__ uint32_t sm[];
    uint32_t* Qs = sm;                     // [BQ][SKT] permuted
    uint32_t* Ks = Qs + BQ * SKT;          // [64][SKT] permuted
    uint32_t* Vs = Ks + 64 * SKT;          // [64][SKT] natural
    uint32_t* Ps = Vs + 64 * SKT;          // [BQ][SKT] permuted

    const int qt = (gridDim.x - 1) - blockIdx.x;  // longest CTAs first
    const int h  = blockIdx.y;
    const int b  = blockIdx.z;
    const int q0 = qt * BQ;
    const int tid  = threadIdx.x;
    const int lane = tid & 31;
    const int w    = tid >> 5;
    const int l4   = lane & 3;
    const int l2   = lane >> 2;
    const int lrow0 = w * 16 + l2;
    const int lrow1 = lrow0 + 8;

    // ---- load Q (pre-scaled tf32 patterns) into permuted smem ----
    const size_t qbase = ((size_t)(b * SEQ + q0)) * DIM + h * HDIM;
#pragma unroll
    for (int v = 0; v < 8; v++) {
        int i = tid + v * 256;
        int r = i >> 4, cv = i & 15;
        uint4 qv = *(const uint4*)(Q + qbase + (size_t)r * DIM + cv * 4);
        uint32_t* dst = Qs + r * SKT + 8 * (cv >> 1) + (cv & 1);
        dst[0] = qv.x; dst[2] = qv.y; dst[4] = qv.z; dst[6] = qv.w;
    }

    float mr0 = -1.0e30f, mr1 = -1.0e30f, lr0 = 0.f, lr1 = 0.f;
    float oacc[8][4];
#pragma unroll
    for (int n = 0; n < 8; n++)
#pragma unroll
        for (int c = 0; c < 4; c++) oacc[n][c] = 0.f;

    const int ntiles = 2 * qt + 2;
    uint4 kreg[4], vreg[4];

    // prefetch tile 0
    {
        const size_t kb = ((size_t)(b * SEQ)) * (2 * DIM) + h * HDIM;
#pragma unroll
        for (int v = 0; v < 4; v++) {
            int i = tid + v * 256;
            int r = i >> 4, cv = i & 15;
            kreg[v] = *(const uint4*)(KV + kb + (size_t)r * (2 * DIM) + cv * 4);
            vreg[v] = *(const uint4*)(KV + kb + DIM + (size_t)r * (2 * DIM) + cv * 4);
        }
    }

    for (int kt = 0; kt < ntiles; kt++) {
        __syncthreads();   // prior tile's smem consumers done (also covers Q store, iter 0)
        // store prefetched K (permuted) / V (natural)
#pragma unroll
        for (int v = 0; v < 4; v++) {
            int i = tid + v * 256;
            int r = i >> 4, cv = i & 15;
            uint32_t* kd = Ks + r * SKT + 8 * (cv >> 1) + (cv & 1);
            kd[0] = kreg[v].x; kd[2] = kreg[v].y; kd[4] = kreg[v].z; kd[6] = kreg[v].w;
            *(uint4*)(Vs + r * SKT + cv * 4) = vreg[v];
        }
        __syncthreads();

        // prefetch next tile (overlaps with compute below)
        if (kt + 1 < ntiles) {
            const size_t kb = ((size_t)(b * SEQ + (kt + 1) * 64)) * (2 * DIM) + h * HDIM;
#pragma unroll
            for (int v = 0; v < 4; v++) {
                int i = tid + v * 256;
                int r = i >> 4, cv = i & 15;
                kreg[v] = *(const uint4*)(KV + kb + (size_t)r * (2 * DIM) + cv * 4);
                vreg[v] = *(const uint4*)(KV + kb + DIM + (size_t)r * (2 * DIM) + cv * 4);
            }
        }

        const int k0 = kt * 64;
        const bool active = (k0 <= q0 + w * 16 + 15);
        if (active) {
            // ---- S = Q K^T (warp: 16 x 64) ----
            float sacc[8][4];
#pragma unroll
            for (int n = 0; n < 8; n++)
#pragma unroll
                for (int c = 0; c < 4; c++) sacc[n][c] = 0.f;

#pragma unroll
            for (int kk = 0; kk < 8; kk++) {
                uint2 a01 = *(const uint2*)(Qs + lrow0 * SKT + kk * 8 + 2 * l4);
                uint2 a23 = *(const uint2*)(Qs + lrow1 * SKT + kk * 8 + 2 * l4);
                uint32_t a[4] = {a01.x, a23.x, a01.y, a23.y};
#pragma unroll
                for (int n = 0; n < 8; n++) {
                    uint2 bv = *(const uint2*)(Ks + (n * 8 + l2) * SKT + kk * 8 + 2 * l4);
                    uint32_t bb[2] = {bv.x, bv.y};
                    mma8(sacc[n], a, bb);
                }
            }

            // ---- causal mask ----
            if (k0 + 63 > q0 + w * 16) {
                const int g0 = q0 + lrow0, g1 = q0 + lrow1;
#pragma unroll
                for (int n = 0; n < 8; n++) {
                    int cg = k0 + n * 8 + 2 * l4;
                    if (cg     > g0) sacc[n][0] = -1.0e30f;
                    if (cg + 1 > g0) sacc[n][1] = -1.0e30f;
                    if (cg     > g1) sacc[n][2] = -1.0e30f;
                    if (cg + 1 > g1) sacc[n][3] = -1.0e30f;
                }
            }

            // ---- online softmax (log2 domain) ----
            float mx0 = -1.0e30f, mx1 = -1.0e30f;
#pragma unroll
            for (int n = 0; n < 8; n++) {
                mx0 = fmaxf(mx0, fmaxf(sacc[n][0], sacc[n][1]));
                mx1 = fmaxf(mx1, fmaxf(sacc[n][2], sacc[n][3]));
            }
            mx0 = fmaxf(mx0, __shfl_xor_sync(0xffffffffu, mx0, 1));
            mx0 = fmaxf(mx0, __shfl_xor_sync(0xffffffffu, mx0, 2));
            mx1 = fmaxf(mx1, __shfl_xor_sync(0xffffffffu, mx1, 1));
            mx1 = fmaxf(mx1, __shfl_xor_sync(0xffffffffu, mx1, 2));

            float mn0 = fmaxf(mr0, mx0), mn1 = fmaxf(mr1, mx1);
            float al0 = ex2(mr0 - mn0),  al1 = ex2(mr1 - mn1);
            float s0 = 0.f, s1 = 0.f;
#pragma unroll
            for (int n = 0; n < 8; n++) {
                float p0 = ex2(sacc[n][0] - mn0);
                float p1 = ex2(sacc[n][1] - mn0);
                float p2 = ex2(sacc[n][2] - mn1);
                float p3 = ex2(sacc[n][3] - mn1);
                sacc[n][0] = p0; sacc[n][1] = p1; sacc[n][2] = p2; sacc[n][3] = p3;
                s0 += p0 + p1;
                s1 += p2 + p3;
            }
            s0 += __shfl_xor_sync(0xffffffffu, s0, 1);
            s0 += __shfl_xor_sync(0xffffffffu, s0, 2);
            s1 += __shfl_xor_sync(0xffffffffu, s1, 1);
            s1 += __shfl_xor_sync(0xffffffffu, s1, 2);
            lr0 = lr0 * al0 + s0;
            lr1 = lr1 * al1 + s1;
            mr0 = mn0; mr1 = mn1;

#pragma unroll
            for (int n = 0; n < 8; n++) {
                oacc[n][0] *= al0; oacc[n][1] *= al0;
                oacc[n][2] *= al1; oacc[n][3] *= al1;
            }

            // ---- write P (permuted, warp-private rows) ----
            const int p0off = (l4 < 2) ? 4 * l4 : 4 * l4 - 7;
#pragma unroll
            for (int n = 0; n < 8; n++) {
                uint32_t* r0p = Ps + lrow0 * SKT + n * 8 + p0off;
                uint32_t* r1p = Ps + lrow1 * SKT + n * 8 + p0off;
                r0p[0] = f2t(sacc[n][0]); r0p[2] = f2t(sacc[n][1]);
                r1p[0] = f2t(sacc[n][2]); r1p[2] = f2t(sacc[n][3]);
            }
            __syncwarp();

            // ---- O += P @ V ----
#pragma unroll
            for (int kk = 0; kk < 8; kk++) {
                uint2 a01 = *(const uint2*)(Ps + lrow0 * SKT + kk * 8 + 2 * l4);
                uint2 a23 = *(const uint2*)(Ps + lrow1 * SKT + kk * 8 + 2 * l4);
                uint32_t a[4] = {a01.x, a23.x, a01.y, a23.y};
                const uint32_t* vb0 = Vs + (kk * 8 + l4) * SKT + l2;
                const uint32_t* vb1 = vb0 + 4 * SKT;
#pragma unroll
                for (int n = 0; n < 8; n++) {
                    uint32_t bb[2] = {vb0[n * 8], vb1[n * 8]};
                    mma8(oacc[n], a, bb);
                }
            }
            __syncwarp();
        }
    }

    // ---- epilogue: normalize, emit ctx as tf32 patterns ----
    const float inv0 = 1.f / lr0, inv1 = 1.f / lr1;
    const size_t ob0 = ((size_t)(b * SEQ + q0 + lrow0)) * DIM + h * HDIM;
    const size_t ob1 = ((size_t)(b * SEQ + q0 + lrow1)) * DIM + h * HDIM;
#pragma unroll
    for (int n = 0; n < 8; n++) {
        int col = n * 8 + 2 * l4;
        *(float2*)&Ctx[ob0 + col] = make_float2(__uint_as_float(f2t(oacc[n][0] * inv0)),
                                                __uint_as_float(f2t(oacc[n][1] * inv0)));
        *(float2*)&Ctx[ob1 + col] = make_float2(__uint_as_float(f2t(oacc[n][2] * inv1)),
                                                __uint_as_float(f2t(oacc[n][3] * inv1)));
    }
}

// ---------------- host launcher ----------------
extern "C" void kernel_launch(void* const* d_in, const int* in_sizes, int n_in,
                              void* d_out, int out_size)
{
    const float* x     = (const float*)d_in[0];
    // d_in[1] = mask (causal, hard-coded)
    const float* w_kvc = (const float*)d_in[2];
    const float* b_kvc = (const float*)d_in[3];
    const float* w_kvu = (const float*)d_in[4];
    const float* b_kvu = (const float*)d_in[5];
    const float* w_qc  = (const float*)d_in[6];
    const float* b_qc  = (const float*)d_in[7];
    const float* w_qu  = (const float*)d_in[8];
    const float* b_qu  = (const float*)d_in[9];
    const float* w_o   = (const float*)d_in[10];
    const float* b_o   = (const float*)d_in[11];
    float* out = (float*)d_out;

    float *lat, *kvup, *qc, *q, *ctx;
    uint32_t *xt, *wkvc, *wqc, *wkvu, *wqu, *wo;
    cudaGetSymbolAddress((void**)&lat,  g_lat);
    cudaGetSymbolAddress((void**)&kvup, g_kvup);
    cudaGetSymbolAddress((void**)&qc,   g_qc);
    cudaGetSymbolAddress((void**)&q,    g_q);
    cudaGetSymbolAddress((void**)&ctx,  g_ctx);
    cudaGetSymbolAddress((void**)&xt,   g_xt);
    cudaGetSymbolAddress((void**)&wkvc, g_wkvc);
    cudaGetSymbolAddress((void**)&wqc,  g_wqc);
    cudaGetSymbolAddress((void**)&wkvu, g_wkvu);
    cudaGetSymbolAddress((void**)&wqu,  g_wqu);
    cudaGetSymbolAddress((void**)&wo,   g_wo);

    cudaFuncSetAttribute(flash_tf32_kernel, cudaFuncAttributeMaxDynamicSharedMemorySize, FL_SMEM);

    // 0. converts to tf32
    auto cvt = [](const float* s, uint32_t* d, int n) {
        cvt_tf32_kernel<<<(n / 4 + 255) / 256, 256>>>((const float4*)s, (uint4*)d, n / 4);
    };
    cvt(x,     xt,   T_TOK * DIM);
    cvt(w_kvc, wkvc, DIM * LATENT);
    cvt(w_qc,  wqc,  DIM * QRANK);
    cvt(w_kvu, wkvu, LATENT * 2 * DIM);
    cvt(w_qu,  wqu,  QRANK * DIM);
    cvt(w_o,   wo,   DIM * DIM);

    // 1+3. fused: kv_latent [8192,128] and q_c [8192,256], both tf32-out
    fused_latqc_kernel<<<dim3(3, T_TOK / 128), 256, GEMM_SMEM>>>(
        xt, wkvc, b_kvc, lat, wqc, b_qc, qc);
    // 2. kv_up = lat @ w_kvu + b  [8192,2048] tf32-out
    gemm_tt_kernel<1><<<dim3(2 * DIM / 128, T_TOK / 128), 256, GEMM_SMEM>>>(
        (const uint32_t*)lat, wkvu, b_kvu, kvup, 2 * DIM, LATENT, 1.f);
    // 4. Q = q_c @ w_qu + b  [8192,1024] tf32-out * (log2e/8)
    gemm_tt_kernel<1><<<dim3(DIM / 128, T_TOK / 128), 256, GEMM_SMEM>>>(
        (const uint32_t*)qc, wqu, b_qu, q, DIM, QRANK, QSCALE);
    // 5. causal flash attention -> ctx (tf32-out)
    flash_tf32_kernel<<<dim3(SEQ / BQ, NHEADS, NBATCH), 256, FL_SMEM>>>(
        (const uint32_t*)q, (const uint32_t*)kvup, ctx);
    // 6. out = ctx @ w_o + b  [8192,1024] fp32
    gemm_tt_kernel<0><<<dim3(DIM / 128, T_TOK / 128), 256, GEMM_SMEM>>>(
        (const uint32_t*)ctx, wo, b_o, out, DIM, DIM, 1.f);
}

// round 6
// speedup vs baseline: 3.4938x; 1.1441x over previous
#include <cuda_runtime.h>
#include <cuda_bf16.h>
#include <cstdint>

// ---------------- problem constants ----------------
#define T_TOK   8192      // B*S
#define SEQ     2048
#define NBATCH  4
#define DIM     1024
#define NHEADS  16
#define HDIM    64
#define LATENT  128
#define QRANK   256

#define QSCALE  0.18033688011112042f   // (1/sqrt(64)) * log2(e)

// ---------------- scratch (device globals; no allocation) ----------------
__device__ float g_lat [T_TOK * LATENT];        // tf32 patterns
__device__ float g_kvup[T_TOK * 2 * DIM];       // tf32 patterns [K | V]
__device__ float g_qc  [T_TOK * QRANK];         // tf32 patterns
__device__ float g_q   [T_TOK * DIM];           // tf32 patterns, pre-scaled by QSCALE
__device__ float g_ctx [T_TOK * DIM];           // tf32 patterns
__device__ uint32_t g_xt  [T_TOK * DIM];        // x as tf32
__device__ uint32_t g_wkvc[DIM * LATENT];
__device__ uint32_t g_wqc [DIM * QRANK];
__device__ uint32_t g_wkvu[LATENT * 2 * DIM];
__device__ uint32_t g_wqu [QRANK * DIM];
__device__ uint32_t g_wo  [DIM * DIM];

// ---------------- helpers ----------------
__device__ __forceinline__ uint32_t f2t(float x) {
    uint32_t u;
    asm("cvt.rna.tf32.f32 %0, %1;" : "=r"(u) : "f"(x));
    return u;
}
__device__ __forceinline__ float ex2(float x) {
    float r;
    asm("ex2.approx.f32 %0, %1;" : "=f"(r) : "f"(x));
    return r;
}
__device__ __forceinline__ void mma8(float* c, const uint32_t* a, const uint32_t* b) {
    asm volatile(
        "mma.sync.aligned.m16n8k8.row.col.f32.tf32.tf32.f32 "
        "{%0,%1,%2,%3}, {%4,%5,%6,%7}, {%8,%9}, {%0,%1,%2,%3};"
        : "+f"(c[0]), "+f"(c[1]), "+f"(c[2]), "+f"(c[3])
        : "r"(a[0]), "r"(a[1]), "r"(a[2]), "r"(a[3]), "r"(b[0]), "r"(b[1]));
}
__device__ __forceinline__ void ldsm4(uint32_t* r, uint32_t saddr) {
    asm volatile("ldmatrix.sync.aligned.m8n8.x4.shared.b16 {%0,%1,%2,%3}, [%4];"
        : "=r"(r[0]), "=r"(r[1]), "=r"(r[2]), "=r"(r[3]) : "r"(saddr));
}

// ---------------- fp32 -> tf32 converts ----------------
__global__ void cvt_x_kernel(const float4* __restrict__ src, uint4* __restrict__ dst, int n4)
{
    int i = blockIdx.x * 256 + threadIdx.x;
    if (i < n4) {
        float4 v = src[i];
        uint4 u;
        u.x = f2t(v.x); u.y = f2t(v.y); u.z = f2t(v.z); u.w = f2t(v.w);
        dst[i] = u;
    }
}

// all 5 weight matrices in one launch (segmented)
__global__ void cvt_w_kernel(
    const float4* s0, uint4* d0, int n0,
    const float4* s1, uint4* d1, int n1,
    const float4* s2, uint4* d2, int n2,
    const float4* s3, uint4* d3, int n3,
    const float4* s4, uint4* d4, int n4)
{
    int i = blockIdx.x * 256 + threadIdx.x;
    const float4* s; uint4* d;
    if (i < n0)                { s = s0; d = d0; }
    else if ((i -= n0) < n1)   { s = s1; d = d1; }
    else if ((i -= n1) < n2)   { s = s2; d = d2; }
    else if ((i -= n2) < n3)   { s = s3; d = d3; }
    else if ((i -= n3) < n4)   { s = s4; d = d4; }
    else return;
    float4 v = s[i];
    uint4 u;
    u.x = f2t(v.x); u.y = f2t(v.y); u.z = f2t(v.z); u.w = f2t(v.w);
    d[i] = u;
}

// ---------------- GEMM body: C = A[M,K](tf32) @ W[K,N](tf32) + bias ----------------
// A smem: natural [m][k], stride 36 (conflict-free STS.128 and LDSM).
// B smem: [k][n], stride 132 (proven round-5 layout).
// Block tile 128x128, BK=32, 256 threads, warp tile 64x32, register-prefetch.
// MODE 0: store fp32.  MODE 1: store tf32 bit pattern of scale*(acc+bias).
#define A_STR 36
#define B_STR 132
#define A_WORDS (128 * A_STR)     // 4608
#define GEMM_SMEM ((128 * A_STR + 32 * B_STR) * 4)   // 35328 B

template<int MODE>
__device__ __forceinline__ void gemm_body(
    const uint32_t* __restrict__ A, const uint32_t* __restrict__ W,
    const float* __restrict__ bias, float* __restrict__ C,
    int N, int K, int m0, int n0, float scale, uint32_t* As, uint32_t* Bs)
{
    const int tid  = threadIdx.x;
    const int lane = tid & 31;
    const int wid  = tid >> 5;
    const int wm   = (wid >> 2) * 64;
    const int wn   = (wid & 3) * 32;
    const int l4   = lane & 3;
    const int l2   = lane >> 2;

    const int ar0 = tid >> 3;          // A row base (+32 per v)
    const int ca  = (tid & 7) * 4;     // A col base
    const int br0 = tid >> 5;          // B row base (+8 per v)
    const int cb  = (tid & 31) * 4;    // B col base

    // LDSM lane addressing: matrix = lane>>3 (a0..a3), row-in-matrix = lane&7
    const int lrow = ((lane >> 3) & 1) * 8 + (lane & 7);   // m offset within 16-row frag
    const int lcol = (lane >> 4) * 4;                      // k offset (0 or 4)
    const uint32_t asb = (uint32_t)__cvta_generic_to_shared(As);

    float acc[4][4][4];
#pragma unroll
    for (int i = 0; i < 4; i++)
#pragma unroll
        for (int j = 0; j < 4; j++)
#pragma unroll
            for (int c = 0; c < 4; c++) acc[i][j][c] = 0.f;

    const int nk = K >> 5;
    uint4 areg[4], breg[4];

    auto gload = [&](int k0) {
#pragma unroll
        for (int v = 0; v < 4; v++) {
            areg[v] = *(const uint4*)(A + (size_t)(m0 + ar0 + v * 32) * K + k0 + ca);
            breg[v] = *(const uint4*)(W + (size_t)(k0 + br0 + v * 8) * N + n0 + cb);
        }
    };

    gload(0);
    for (int kt = 0; kt < nk; kt++) {
        __syncthreads();   // previous compute done reading smem
#pragma unroll
        for (int v = 0; v < 4; v++) {
            *(uint4*)(As + (ar0 + v * 32) * A_STR + ca)  = areg[v];
            *(uint4*)(Bs + (br0 + v * 8) * B_STR + cb)   = breg[v];
        }
        __syncthreads();

        if (kt + 1 < nk) gload((kt + 1) << 5);   // overlap LDG with MMAs

#pragma unroll
        for (int kk = 0; kk < 4; kk++) {
            const int k = kk * 8;
            uint32_t af[4][4], bf[4][2];
#pragma unroll
            for (int im = 0; im < 4; im++)
                ldsm4(af[im], asb + ((wm + im * 16 + lrow) * A_STR + k + lcol) * 4);
#pragma unroll
            for (int in = 0; in < 4; in++) {
                int n = wn + in * 8 + l2;
                bf[in][0] = Bs[(k + l4) * B_STR + n];
                bf[in][1] = Bs[(k + l4 + 4) * B_STR + n];
            }
#pragma unroll
            for (int im = 0; im < 4; im++)
#pragma unroll
                for (int in = 0; in < 4; in++)
                    mma8(acc[im][in], af[im], bf[in]);
        }
    }

#pragma unroll
    for (int im = 0; im < 4; im++) {
        int row = m0 + wm + im * 16 + l2;
#pragma unroll
        for (int in = 0; in < 4; in++) {
            int col = n0 + wn + in * 8 + 2 * l4;
            float b0 = bias[col], b1 = bias[col + 1];
            float2 v0, v1;
            if (MODE == 0) {
                v0 = make_float2(acc[im][in][0] + b0, acc[im][in][1] + b1);
                v1 = make_float2(acc[im][in][2] + b0, acc[im][in][3] + b1);
            } else {
                v0 = make_float2(__uint_as_float(f2t(scale * (acc[im][in][0] + b0))),
                                 __uint_as_float(f2t(scale * (acc[im][in][1] + b1))));
                v1 = make_float2(__uint_as_float(f2t(scale * (acc[im][in][2] + b0))),
                                 __uint_as_float(f2t(scale * (acc[im][in][3] + b1))));
            }
            *(float2*)&C[(size_t)row * N + col]       = v0;
            *(float2*)&C[(size_t)(row + 8) * N + col] = v1;
        }
    }
}

template<int MODE>
__global__ __launch_bounds__(256, 2)
void gemm_tt_kernel(const uint32_t* __restrict__ A, const uint32_t* __restrict__ W,
                    const float* __restrict__ bias, float* __restrict__ C,
                    int N, int K, float scale)
{
    extern __shared__ uint32_t smg[];
    gemm_body<MODE>(A, W, bias, C, N, K, blockIdx.y * 128, blockIdx.x * 128, scale,
                    smg, smg + A_WORDS);
}

// fused kv_latent (N=128) + q_c (N=256): grid.x = 3 column tiles, K=1024
__global__ __launch_bounds__(256, 2)
void fused_latqc_kernel(const uint32_t* __restrict__ X,
                        const uint32_t* __restrict__ Wkvc, const float* __restrict__ bkvc, float* __restrict__ lat,
                        const uint32_t* __restrict__ Wqc,  const float* __restrict__ bqc,  float* __restrict__ qc)
{
    extern __shared__ uint32_t smg[];
    const int bx = blockIdx.x;
    if (bx == 0)
        gemm_body<1>(X, Wkvc, bkvc, lat, LATENT, DIM, blockIdx.y * 128, 0, 1.f,
                     smg, smg + A_WORDS);
    else
        gemm_body<1>(X, Wqc, bqc, qc, QRANK, DIM, blockIdx.y * 128, (bx - 1) * 128, 1.f,
                     smg, smg + A_WORDS);
}

// ---------------- causal flash attention, tf32, hd=64 (round-5 proven, unchanged) ----------------
#define BQ   128
#define SKT  72
#define FL_SMEM ((2 * BQ + 2 * 64) * SKT * 4)   // 110592 B

__global__ __launch_bounds__(256, 2)
void flash_tf32_kernel(const uint32_t* __restrict__ Q, const uint32_t* __restrict__ KV,
                       float* __restrict__ Ctx)
{
    extern __shared__ uint32_t sm[];
    uint32_t* Qs = sm;                     // [BQ][SKT] permuted
    uint32_t* Ks = Qs + BQ * SKT;          // [64][SKT] permuted
    uint32_t* Vs = Ks + 64 * SKT;          // [64][SKT] natural
    uint32_t* Ps = Vs + 64 * SKT;          // [BQ][SKT] permuted

    const int qt = (gridDim.x - 1) - blockIdx.x;  // longest CTAs first
    const int h  = blockIdx.y;
    const int b  = blockIdx.z;
    const int q0 = qt * BQ;
    const int tid  = threadIdx.x;
    const int lane = tid & 31;
    const int w    = tid >> 5;
    const int l4   = lane & 3;
    const int l2   = lane >> 2;
    const int lrow0 = w * 16 + l2;
    const int lrow1 = lrow0 + 8;

    const size_t qbase = ((size_t)(b * SEQ + q0)) * DIM + h * HDIM;
#pragma unroll
    for (int v = 0; v < 8; v++) {
        int i = tid + v * 256;
        int r = i >> 4, cv = i & 15;
        uint4 qv = *(const uint4*)(Q + qbase + (size_t)r * DIM + cv * 4);
        uint32_t* dst = Qs + r * SKT + 8 * (cv >> 1) + (cv & 1);
        dst[0] = qv.x; dst[2] = qv.y; dst[4] = qv.z; dst[6] = qv.w;
    }

    float mr0 = -1.0e30f, mr1 = -1.0e30f, lr0 = 0.f, lr1 = 0.f;
    float oacc[8][4];
#pragma unroll
    for (int n = 0; n < 8; n++)
#pragma unroll
        for (int c = 0; c < 4; c++) oacc[n][c] = 0.f;

    const int ntiles = 2 * qt + 2;
    uint4 kreg[4], vreg[4];

    {
        const size_t kb = ((size_t)(b * SEQ)) * (2 * DIM) + h * HDIM;
#pragma unroll
        for (int v = 0; v < 4; v++) {
            int i = tid + v * 256;
            int r = i >> 4, cv = i & 15;
            kreg[v] = *(const uint4*)(KV + kb + (size_t)r * (2 * DIM) + cv * 4);
            vreg[v] = *(const uint4*)(KV + kb + DIM + (size_t)r * (2 * DIM) + cv * 4);
        }
    }

    for (int kt = 0; kt < ntiles; kt++) {
        __syncthreads();
#pragma unroll
        for (int v = 0; v < 4; v++) {
            int i = tid + v * 256;
            int r = i >> 4, cv = i & 15;
            uint32_t* kd = Ks + r * SKT + 8 * (cv >> 1) + (cv & 1);
            kd[0] = kreg[v].x; kd[2] = kreg[v].y; kd[4] = kreg[v].z; kd[6] = kreg[v].w;
            *(uint4*)(Vs + r * SKT + cv * 4) = vreg[v];
        }
        __syncthreads();

        if (kt + 1 < ntiles) {
            const size_t kb = ((size_t)(b * SEQ + (kt + 1) * 64)) * (2 * DIM) + h * HDIM;
#pragma unroll
            for (int v = 0; v < 4; v++) {
                int i = tid + v * 256;
                int r = i >> 4, cv = i & 15;
                kreg[v] = *(const uint4*)(KV + kb + (size_t)r * (2 * DIM) + cv * 4);
                vreg[v] = *(const uint4*)(KV + kb + DIM + (size_t)r * (2 * DIM) + cv * 4);
            }
        }

        const int k0 = kt * 64;
        const bool active = (k0 <= q0 + w * 16 + 15);
        if (active) {
            float sacc[8][4];
#pragma unroll
            for (int n = 0; n < 8; n++)
#pragma unroll
                for (int c = 0; c < 4; c++) sacc[n][c] = 0.f;

#pragma unroll
            for (int kk = 0; kk < 8; kk++) {
                uint2 a01 = *(const uint2*)(Qs + lrow0 * SKT + kk * 8 + 2 * l4);
                uint2 a23 = *(const uint2*)(Qs + lrow1 * SKT + kk * 8 + 2 * l4);
                uint32_t a[4] = {a01.x, a23.x, a01.y, a23.y};
#pragma unroll
                for (int n = 0; n < 8; n++) {
                    uint2 bv = *(const uint2*)(Ks + (n * 8 + l2) * SKT + kk * 8 + 2 * l4);
                    uint32_t bb[2] = {bv.x, bv.y};
                    mma8(sacc[n], a, bb);
                }
            }

            if (k0 + 63 > q0 + w * 16) {
                const int g0 = q0 + lrow0, g1 = q0 + lrow1;
#pragma unroll
                for (int n = 0; n < 8; n++) {
                    int cg = k0 + n * 8 + 2 * l4;
                    if (cg     > g0) sacc[n][0] = -1.0e30f;
                    if (cg + 1 > g0) sacc[n][1] = -1.0e30f;
                    if (cg     > g1) sacc[n][2] = -1.0e30f;
                    if (cg + 1 > g1) sacc[n][3] = -1.0e30f;
                }
            }

            float mx0 = -1.0e30f, mx1 = -1.0e30f;
#pragma unroll
            for (int n = 0; n < 8; n++) {
                mx0 = fmaxf(mx0, fmaxf(sacc[n][0], sacc[n][1]));
                mx1 = fmaxf(mx1, fmaxf(sacc[n][2], sacc[n][3]));
            }
            mx0 = fmaxf(mx0, __shfl_xor_sync(0xffffffffu, mx0, 1));
            mx0 = fmaxf(mx0, __shfl_xor_sync(0xffffffffu, mx0, 2));
            mx1 = fmaxf(mx1, __shfl_xor_sync(0xffffffffu, mx1, 1));
            mx1 = fmaxf(mx1, __shfl_xor_sync(0xffffffffu, mx1, 2));

            float mn0 = fmaxf(mr0, mx0), mn1 = fmaxf(mr1, mx1);
            float al0 = ex2(mr0 - mn0),  al1 = ex2(mr1 - mn1);
            float s0 = 0.f, s1 = 0.f;
#pragma unroll
            for (int n = 0; n < 8; n++) {
                float p0 = ex2(sacc[n][0] - mn0);
                float p1 = ex2(sacc[n][1] - mn0);
                float p2 = ex2(sacc[n][2] - mn1);
                float p3 = ex2(sacc[n][3] - mn1);
                sacc[n][0] = p0; sacc[n][1] = p1; sacc[n][2] = p2; sacc[n][3] = p3;
                s0 += p0 + p1;
                s1 += p2 + p3;
            }
            s0 += __shfl_xor_sync(0xffffffffu, s0, 1);
            s0 += __shfl_xor_sync(0xffffffffu, s0, 2);
            s1 += __shfl_xor_sync(0xffffffffu, s1, 1);
            s1 += __shfl_xor_sync(0xffffffffu, s1, 2);
            lr0 = lr0 * al0 + s0;
            lr1 = lr1 * al1 + s1;
            mr0 = mn0; mr1 = mn1;

#pragma unroll
            for (int n = 0; n < 8; n++) {
                oacc[n][0] *= al0; oacc[n][1] *= al0;
                oacc[n][2] *= al1; oacc[n][3] *= al1;
            }

            const int p0off = (l4 < 2) ? 4 * l4 : 4 * l4 - 7;
#pragma unroll
            for (int n = 0; n < 8; n++) {
                uint32_t* r0p = Ps + lrow0 * SKT + n * 8 + p0off;
                uint32_t* r1p = Ps + lrow1 * SKT + n * 8 + p0off;
                r0p[0] = f2t(sacc[n][0]); r0p[2] = f2t(sacc[n][1]);
                r1p[0] = f2t(sacc[n][2]); r1p[2] = f2t(sacc[n][3]);
            }
            __syncwarp();

#pragma unroll
            for (int kk = 0; kk < 8; kk++) {
                uint2 a01 = *(const uint2*)(Ps + lrow0 * SKT + kk * 8 + 2 * l4);
                uint2 a23 = *(const uint2*)(Ps + lrow1 * SKT + kk * 8 + 2 * l4);
                uint32_t a[4] = {a01.x, a23.x, a01.y, a23.y};
                const uint32_t* vb0 = Vs + (kk * 8 + l4) * SKT + l2;
                const uint32_t* vb1 = vb0 + 4 * SKT;
#pragma unroll
                for (int n = 0; n < 8; n++) {
                    uint32_t bb[2] = {vb0[n * 8], vb1[n * 8]};
                    mma8(oacc[n], a, bb);
                }
            }
            __syncwarp();
        }
    }

    const float inv0 = 1.f / lr0, inv1 = 1.f / lr1;
    const size_t ob0 = ((size_t)(b * SEQ + q0 + lrow0)) * DIM + h * HDIM;
    const size_t ob1 = ((size_t)(b * SEQ + q0 + lrow1)) * DIM + h * HDIM;
#pragma unroll
    for (int n = 0; n < 8; n++) {
        int col = n * 8 + 2 * l4;
        *(float2*)&Ctx[ob0 + col] = make_float2(__uint_as_float(f2t(oacc[n][0] * inv0)),
                                                __uint_as_float(f2t(oacc[n][1] * inv0)));
        *(float2*)&Ctx[ob1 + col] = make_float2(__uint_as_float(f2t(oacc[n][2] * inv1)),
                                                __uint_as_float(f2t(oacc[n][3] * inv1)));
    }
}

// ---------------- host launcher ----------------
extern "C" void kernel_launch(void* const* d_in, const int* in_sizes, int n_in,
                              void* d_out, int out_size)
{
    const float* x     = (const float*)d_in[0];
    // d_in[1] = mask (causal, hard-coded)
    const float* w_kvc = (const float*)d_in[2];
    const float* b_kvc = (const float*)d_in[3];
    const float* w_kvu = (const float*)d_in[4];
    const float* b_kvu = (const float*)d_in[5];
    const float* w_qc  = (const float*)d_in[6];
    const float* b_qc  = (const float*)d_in[7];
    const float* w_qu  = (const float*)d_in[8];
    const float* b_qu  = (const float*)d_in[9];
    const float* w_o   = (const float*)d_in[10];
    const float* b_o   = (const float*)d_in[11];
    float* out = (float*)d_out;

    float *lat, *kvup, *qc, *q, *ctx;
    uint32_t *xt, *wkvc, *wqc, *wkvu, *wqu, *wo;
    cudaGetSymbolAddress((void**)&lat,  g_lat);
    cudaGetSymbolAddress((void**)&kvup, g_kvup);
    cudaGetSymbolAddress((void**)&qc,   g_qc);
    cudaGetSymbolAddress((void**)&q,    g_q);
    cudaGetSymbolAddress((void**)&ctx,  g_ctx);
    cudaGetSymbolAddress((void**)&xt,   g_xt);
    cudaGetSymbolAddress((void**)&wkvc, g_wkvc);
    cudaGetSymbolAddress((void**)&wqc,  g_wqc);
    cudaGetSymbolAddress((void**)&wkvu, g_wkvu);
    cudaGetSymbolAddress((void**)&wqu,  g_wqu);
    cudaGetSymbolAddress((void**)&wo,   g_wo);

    cudaFuncSetAttribute(flash_tf32_kernel, cudaFuncAttributeMaxDynamicSharedMemorySize, FL_SMEM);

    // launch 0: all weight converts (segmented, one kernel)
    const int nw0 = DIM * LATENT / 4, nw1 = DIM * QRANK / 4, nw2 = LATENT * 2 * DIM / 4;
    const int nw3 = QRANK * DIM / 4,  nw4 = DIM * DIM / 4;
    const int nwt = nw0 + nw1 + nw2 + nw3 + nw4;
    cvt_w_kernel<<<(nwt + 255) / 256, 256>>>(
        (const float4*)w_kvc, (uint4*)wkvc, nw0,
        (const float4*)w_qc,  (uint4*)wqc,  nw1,
        (const float4*)w_kvu, (uint4*)wkvu, nw2,
        (const float4*)w_qu,  (uint4*)wqu,  nw3,
        (const float4*)w_o,   (uint4*)wo,   nw4);
    // launch 1: x convert
    cvt_x_kernel<<<(T_TOK * DIM / 4 + 255) / 256, 256>>>((const float4*)x, (uint4*)xt, T_TOK * DIM / 4);

    // launch 2: fused kv_latent [8192,128] + q_c [8192,256], tf32-out
    fused_latqc_kernel<<<dim3(3, T_TOK / 128), 256, GEMM_SMEM>>>(
        xt, wkvc, b_kvc, lat, wqc, b_qc, qc);
    // launch 3: kv_up = lat @ w_kvu + b  [8192,2048] tf32-out
    gemm_tt_kernel<1><<<dim3(2 * DIM / 128, T_TOK / 128), 256, GEMM_SMEM>>>(
        (const uint32_t*)lat, wkvu, b_kvu, kvup, 2 * DIM, LATENT, 1.f);
    // launch 4: Q = q_c @ w_qu + b  [8192,1024] tf32-out * (log2e/8)
    gemm_tt_kernel<1><<<dim3(DIM / 128, T_TOK / 128), 256, GEMM_SMEM>>>(
        (const uint32_t*)qc, wqu, b_qu, q, DIM, QRANK, QSCALE);
    // launch 5: causal flash attention -> ctx (tf32-out)  [ncu -s 5 captures this]
    flash_tf32_kernel<<<dim3(SEQ / BQ, NHEADS, NBATCH), 256, FL_SMEM>>>(
        (const uint32_t*)q, (const uint32_t*)kvup, ctx);
    // launch 6: out = ctx @ w_o + b  [8192,1024] fp32
    gemm_tt_kernel<0><<<dim3(DIM / 128, T_TOK / 128), 256, GEMM_SMEM>>>(
        (const uint32_t*)ctx, wo, b_o, out, DIM, DIM, 1.f);
}

// round 7
// speedup vs baseline: 3.8017x; 1.0881x over previous
#include <cuda_runtime.h>
#include <cuda_bf16.h>
#include <cstdint>

// ---------------- problem constants ----------------
#define T_TOK   8192      // B*S
#define SEQ     2048
#define NBATCH  4
#define DIM     1024
#define NHEADS  16
#define HDIM    64
#define LATENT  128
#define QRANK   256

#define QSCALE  0.18033688011112042f   // (1/sqrt(64)) * log2(e)

// ---------------- scratch (device globals; no allocation) ----------------
__device__ float g_lat [T_TOK * LATENT];        // tf32 patterns
__device__ float g_kvup[T_TOK * 2 * DIM];       // tf32 patterns [K | V]
__device__ float g_qc  [T_TOK * QRANK];         // tf32 patterns
__device__ float g_q   [T_TOK * DIM];           // tf32 patterns, pre-scaled by QSCALE
__device__ float g_ctx [T_TOK * DIM];           // tf32 patterns
__device__ uint32_t g_xt  [T_TOK * DIM];        // x as tf32
__device__ uint32_t g_wkvc[DIM * LATENT];       // transposed: [LATENT][DIM]
__device__ uint32_t g_wqc [DIM * QRANK];        // transposed: [QRANK][DIM]
__device__ uint32_t g_wkvu[LATENT * 2 * DIM];   // transposed: [2*DIM][LATENT]
__device__ uint32_t g_wqu [QRANK * DIM];        // transposed: [DIM][QRANK]
__device__ uint32_t g_wo  [DIM * DIM];          // transposed: [DIM][DIM]

// ---------------- helpers ----------------
__device__ __forceinline__ uint32_t f2t(float x) {
    uint32_t u;
    asm("cvt.rna.tf32.f32 %0, %1;" : "=r"(u) : "f"(x));
    return u;
}
__device__ __forceinline__ float ex2(float x) {
    float r;
    asm("ex2.approx.f32 %0, %1;" : "=f"(r) : "f"(x));
    return r;
}
__device__ __forceinline__ void mma8(float* c, const uint32_t* a, const uint32_t* b) {
    asm volatile(
        "mma.sync.aligned.m16n8k8.row.col.f32.tf32.tf32.f32 "
        "{%0,%1,%2,%3}, {%4,%5,%6,%7}, {%8,%9}, {%0,%1,%2,%3};"
        : "+f"(c[0]), "+f"(c[1]), "+f"(c[2]), "+f"(c[3])
        : "r"(a[0]), "r"(a[1]), "r"(a[2]), "r"(a[3]), "r"(b[0]), "r"(b[1]));
}
__device__ __forceinline__ void ldsm4(uint32_t* r, uint32_t saddr) {
    asm volatile("ldmatrix.sync.aligned.m8n8.x4.shared.b16 {%0,%1,%2,%3}, [%4];"
        : "=r"(r[0]), "=r"(r[1]), "=r"(r[2]), "=r"(r[3]) : "r"(saddr));
}

// ---------------- converts ----------------
__global__ void cvt_x_kernel(const float4* __restrict__ src, uint4* __restrict__ dst, int n4)
{
    int i = blockIdx.x * 256 + threadIdx.x;
    if (i < n4) {
        float4 v = src[i];
        uint4 u;
        u.x = f2t(v.x); u.y = f2t(v.y); u.z = f2t(v.z); u.w = f2t(v.w);
        dst[i] = u;
    }
}

// transpose+convert all 5 weights in one launch: src [K][N] fp32 -> dst [N][K] tf32
__global__ __launch_bounds__(256)
void cvt_wT_kernel(
    const float* s0, uint32_t* d0, int K0, int N0, int t0,
    const float* s1, uint32_t* d1, int K1, int N1, int t1,
    const float* s2, uint32_t* d2, int K2, int N2, int t2,
    const float* s3, uint32_t* d3, int K3, int N3, int t3,
    const float* s4, uint32_t* d4, int K4, int N4)
{
    __shared__ uint32_t tb[32][33];
    int bx = blockIdx.x;
    const float* s; uint32_t* d; int K, N;
    if (bx < t0)              { s = s0; d = d0; K = K0; N = N0; }
    else if ((bx -= t0) < t1) { s = s1; d = d1; K = K1; N = N1; }
    else if ((bx -= t1) < t2) { s = s2; d = d2; K = K2; N = N2; }
    else if ((bx -= t2) < t3) { s = s3; d = d3; K = K3; N = N3; }
    else { bx -= t3;            s = s4; d = d4; K = K4; N = N4; }

    const int nx = N >> 5;
    const int k0 = (bx / nx) * 32, n0 = (bx % nx) * 32;
    const int tx = threadIdx.x & 31, ty = threadIdx.x >> 5;   // 32 x 8
#pragma unroll
    for (int dy = 0; dy < 32; dy += 8)
        tb[ty + dy][tx] = f2t(s[(size_t)(k0 + ty + dy) * N + n0 + tx]);
    __syncthreads();
#pragma unroll
    for (int dy = 0; dy < 32; dy += 8)
        d[(size_t)(n0 + ty + dy) * K + k0 + tx] = tb[tx][ty + dy];
}

// ---------------- GEMM body: C = A[M,K](tf32) @ Wt[N,K](tf32, transposed) + bias ----------------
// Both operands natural-row smem (stride 36), STS.128 staging, ldmatrix fragments.
// Block tile 128x128, BK=32, 256 threads, warp tile 64x32, register-prefetch.
#define A_STR 36
#define A_WORDS (128 * A_STR)     // 4608
#define GEMM_SMEM (2 * A_WORDS * 4)   // 36864 B

template<int MODE>
__device__ __forceinline__ void gemm_body(
    const uint32_t* __restrict__ A, const uint32_t* __restrict__ Wt,
    const float* __restrict__ bias, float* __restrict__ C,
    int N, int K, int m0, int n0, float scale, uint32_t* As, uint32_t* Bs)
{
    const int tid  = threadIdx.x;
    const int lane = tid & 31;
    const int wid  = tid >> 5;
    const int wm   = (wid >> 2) * 64;
    const int wn   = (wid & 3) * 32;
    const int l4   = lane & 3;
    const int l2   = lane >> 2;

    const int ar0 = tid >> 3;          // staging row base (+32 per v)
    const int ca  = (tid & 7) * 4;     // staging col base

    // ldmatrix lane addressing
    const int lrow = ((lane >> 3) & 1) * 8 + (lane & 7);
    const int lcol = (lane >> 4) * 4;
    const uint32_t asb = (uint32_t)__cvta_generic_to_shared(As);
    const uint32_t bsb = (uint32_t)__cvta_generic_to_shared(Bs);

    float acc[4][4][4];
#pragma unroll
    for (int i = 0; i < 4; i++)
#pragma unroll
        for (int j = 0; j < 4; j++)
#pragma unroll
            for (int c = 0; c < 4; c++) acc[i][j][c] = 0.f;

    const int nk = K >> 5;
    uint4 areg[4], breg[4];

    auto gload = [&](int k0) {
#pragma unroll
        for (int v = 0; v < 4; v++) {
            areg[v] = *(const uint4*)(A  + (size_t)(m0 + ar0 + v * 32) * K + k0 + ca);
            breg[v] = *(const uint4*)(Wt + (size_t)(n0 + ar0 + v * 32) * K + k0 + ca);
        }
    };

    gload(0);
    for (int kt = 0; kt < nk; kt++) {
        __syncthreads();
#pragma unroll
        for (int v = 0; v < 4; v++) {
            *(uint4*)(As + (ar0 + v * 32) * A_STR + ca) = areg[v];
            *(uint4*)(Bs + (ar0 + v * 32) * A_STR + ca) = breg[v];
        }
        __syncthreads();

        if (kt + 1 < nk) gload((kt + 1) << 5);

#pragma unroll
        for (int kk = 0; kk < 4; kk++) {
            const int k = kk * 8;
            uint32_t af[4][4], br[2][4];
#pragma unroll
            for (int im = 0; im < 4; im++)
                ldsm4(af[im], asb + ((wm + im * 16 + lrow) * A_STR + k + lcol) * 4);
#pragma unroll
            for (int p = 0; p < 2; p++)
                ldsm4(br[p], bsb + ((wn + p * 16 + lrow) * A_STR + k + lcol) * 4);
            uint32_t bf[4][2] = {
                {br[0][0], br[0][2]}, {br[0][1], br[0][3]},
                {br[1][0], br[1][2]}, {br[1][1], br[1][3]}};
#pragma unroll
            for (int im = 0; im < 4; im++)
#pragma unroll
                for (int in = 0; in < 4; in++)
                    mma8(acc[im][in], af[im], bf[in]);
        }
    }

#pragma unroll
    for (int im = 0; im < 4; im++) {
        int row = m0 + wm + im * 16 + l2;
#pragma unroll
        for (int in = 0; in < 4; in++) {
            int col = n0 + wn + in * 8 + 2 * l4;
            float b0 = bias[col], b1 = bias[col + 1];
            float2 v0, v1;
            if (MODE == 0) {
                v0 = make_float2(acc[im][in][0] + b0, acc[im][in][1] + b1);
                v1 = make_float2(acc[im][in][2] + b0, acc[im][in][3] + b1);
            } else {
                v0 = make_float2(__uint_as_float(f2t(scale * (acc[im][in][0] + b0))),
                                 __uint_as_float(f2t(scale * (acc[im][in][1] + b1))));
                v1 = make_float2(__uint_as_float(f2t(scale * (acc[im][in][2] + b0))),
                                 __uint_as_float(f2t(scale * (acc[im][in][3] + b1))));
            }
            *(float2*)&C[(size_t)row * N + col]       = v0;
            *(float2*)&C[(size_t)(row + 8) * N + col] = v1;
        }
    }
}

template<int MODE>
__global__ __launch_bounds__(256, 2)
void gemm_tt_kernel(const uint32_t* __restrict__ A, const uint32_t* __restrict__ Wt,
                    const float* __restrict__ bias, float* __restrict__ C,
                    int N, int K, float scale)
{
    extern __shared__ uint32_t smg[];
    gemm_body<MODE>(A, Wt, bias, C, N, K, blockIdx.y * 128, blockIdx.x * 128, scale,
                    smg, smg + A_WORDS);
}

// fused kv_latent (N=128) + q_c (N=256)
__global__ __launch_bounds__(256, 2)
void fused_latqc_kernel(const uint32_t* __restrict__ X,
                        const uint32_t* __restrict__ WkvcT, const float* __restrict__ bkvc, float* __restrict__ lat,
                        const uint32_t* __restrict__ WqcT,  const float* __restrict__ bqc,  float* __restrict__ qc)
{
    extern __shared__ uint32_t smg[];
    const int bx = blockIdx.x;
    if (bx == 0)
        gemm_body<1>(X, WkvcT, bkvc, lat, LATENT, DIM, blockIdx.y * 128, 0, 1.f,
                     smg, smg + A_WORDS);
    else
        gemm_body<1>(X, WqcT, bqc, qc, QRANK, DIM, blockIdx.y * 128, (bx - 1) * 128, 1.f,
                     smg, smg + A_WORDS);
}

// ---------------- causal flash attention, tf32, hd=64 ----------------
// BQ=128 q rows/CTA, 8 warps; kv tile 64, register-prefetch double buffer.
// Q/K natural layout + ldmatrix; V natural scalar; P permuted (proven).
#define BQ    128
#define QSTR  68    // mod 32 == 4 -> ldmatrix conflict-free
#define VSTR  72    // mod 32 == 8 -> scalar V frags conflict-free
#define PSTR  72
#define FL_SMEM ((BQ * QSTR + 64 * QSTR + 64 * VSTR + BQ * PSTR) * 4)  // 107520 B

__global__ __launch_bounds__(256, 2)
void flash_tf32_kernel(const uint32_t* __restrict__ Q, const uint32_t* __restrict__ KV,
                       float* __restrict__ Ctx)
{
    extern __shared__ uint32_t sm[];
    uint32_t* Qs = sm;                     // [BQ][QSTR] natural
    uint32_t* Ks = Qs + BQ * QSTR;         // [64][QSTR] natural
    uint32_t* Vs = Ks + 64 * QSTR;         // [64][VSTR] natural
    uint32_t* Ps = Vs + 64 * VSTR;         // [BQ][PSTR] permuted

    const int qt = (gridDim.x - 1) - blockIdx.x;  // longest CTAs first
    const int h  = blockIdx.y;
    const int b  = blockIdx.z;
    const int q0 = qt * BQ;
    const int tid  = threadIdx.x;
    const int lane = tid & 31;
    const int w    = tid >> 5;
    const int l4   = lane & 3;
    const int l2   = lane >> 2;
    const int lrow0 = w * 16 + l2;
    const int lrow1 = lrow0 + 8;

    // ldmatrix lane addressing
    const int lrow = ((lane >> 3) & 1) * 8 + (lane & 7);
    const int lcol = (lane >> 4) * 4;
    const uint32_t qsb = (uint32_t)__cvta_generic_to_shared(Qs);
    const uint32_t ksb = (uint32_t)__cvta_generic_to_shared(Ks);

    // ---- load Q (pre-scaled tf32) natural ----
    const size_t qbase = ((size_t)(b * SEQ + q0)) * DIM + h * HDIM;
#pragma unroll
    for (int v = 0; v < 8; v++) {
        int i = tid + v * 256;
        int r = i >> 4, cv = i & 15;
        uint4 qv = *(const uint4*)(Q + qbase + (size_t)r * DIM + cv * 4);
        *(uint4*)(Qs + r * QSTR + cv * 4) = qv;
    }

    float mr0 = -1.0e30f, mr1 = -1.0e30f, lr0 = 0.f, lr1 = 0.f;
    float oacc[8][4];
#pragma unroll
    for (int n = 0; n < 8; n++)
#pragma unroll
        for (int c = 0; c < 4; c++) oacc[n][c] = 0.f;

    const int ntiles = 2 * qt + 2;
    uint4 kreg[4], vreg[4];

    {
        const size_t kb = ((size_t)(b * SEQ)) * (2 * DIM) + h * HDIM;
#pragma unroll
        for (int v = 0; v < 4; v++) {
            int i = tid + v * 256;
            int r = i >> 4, cv = i & 15;
            kreg[v] = *(const uint4*)(KV + kb + (size_t)r * (2 * DIM) + cv * 4);
            vreg[v] = *(const uint4*)(KV + kb + DIM + (size_t)r * (2 * DIM) + cv * 4);
        }
    }

    for (int kt = 0; kt < ntiles; kt++) {
        __syncthreads();
#pragma unroll
        for (int v = 0; v < 4; v++) {
            int i = tid + v * 256;
            int r = i >> 4, cv = i & 15;
            *(uint4*)(Ks + r * QSTR + cv * 4) = kreg[v];
            *(uint4*)(Vs + r * VSTR + cv * 4) = vreg[v];
        }
        __syncthreads();

        if (kt + 1 < ntiles) {
            const size_t kb = ((size_t)(b * SEQ + (kt + 1) * 64)) * (2 * DIM) + h * HDIM;
#pragma unroll
            for (int v = 0; v < 4; v++) {
                int i = tid + v * 256;
                int r = i >> 4, cv = i & 15;
                kreg[v] = *(const uint4*)(KV + kb + (size_t)r * (2 * DIM) + cv * 4);
                vreg[v] = *(const uint4*)(KV + kb + DIM + (size_t)r * (2 * DIM) + cv * 4);
            }
        }

        const int k0 = kt * 64;
        const bool active = (k0 <= q0 + w * 16 + 15);
        if (active) {
            // ---- S = Q K^T via ldmatrix ----
            float sacc[8][4];
#pragma unroll
            for (int n = 0; n < 8; n++)
#pragma unroll
                for (int c = 0; c < 4; c++) sacc[n][c] = 0.f;

#pragma unroll
            for (int kk = 0; kk < 8; kk++) {
                uint32_t a[4];
                ldsm4(a, qsb + ((w * 16 + lrow) * QSTR + kk * 8 + lcol) * 4);
#pragma unroll
                for (int p = 0; p < 4; p++) {
                    uint32_t kr[4];
                    ldsm4(kr, ksb + ((p * 16 + lrow) * QSTR + kk * 8 + lcol) * 4);
                    uint32_t b0[2] = {kr[0], kr[2]};
                    uint32_t b1[2] = {kr[1], kr[3]};
                    mma8(sacc[2 * p],     a, b0);
                    mma8(sacc[2 * p + 1], a, b1);
                }
            }

            // ---- causal mask ----
            if (k0 + 63 > q0 + w * 16) {
                const int g0 = q0 + lrow0, g1 = q0 + lrow1;
#pragma unroll
                for (int n = 0; n < 8; n++) {
                    int cg = k0 + n * 8 + 2 * l4;
                    if (cg     > g0) sacc[n][0] = -1.0e30f;
                    if (cg + 1 > g0) sacc[n][1] = -1.0e30f;
                    if (cg     > g1) sacc[n][2] = -1.0e30f;
                    if (cg + 1 > g1) sacc[n][3] = -1.0e30f;
                }
            }

            // ---- online softmax (log2 domain) ----
            float mx0 = -1.0e30f, mx1 = -1.0e30f;
#pragma unroll
            for (int n = 0; n < 8; n++) {
                mx0 = fmaxf(mx0, fmaxf(sacc[n][0], sacc[n][1]));
                mx1 = fmaxf(mx1, fmaxf(sacc[n][2], sacc[n][3]));
            }
            mx0 = fmaxf(mx0, __shfl_xor_sync(0xffffffffu, mx0, 1));
            mx0 = fmaxf(mx0, __shfl_xor_sync(0xffffffffu, mx0, 2));
            mx1 = fmaxf(mx1, __shfl_xor_sync(0xffffffffu, mx1, 1));
            mx1 = fmaxf(mx1, __shfl_xor_sync(0xffffffffu, mx1, 2));

            float mn0 = fmaxf(mr0, mx0), mn1 = fmaxf(mr1, mx1);
            float al0 = ex2(mr0 - mn0),  al1 = ex2(mr1 - mn1);
            float s0 = 0.f, s1 = 0.f;
#pragma unroll
            for (int n = 0; n < 8; n++) {
                float p0 = ex2(sacc[n][0] - mn0);
                float p1 = ex2(sacc[n][1] - mn0);
                float p2 = ex2(sacc[n][2] - mn1);
                float p3 = ex2(sacc[n][3] - mn1);
                sacc[n][0] = p0; sacc[n][1] = p1; sacc[n][2] = p2; sacc[n][3] = p3;
                s0 += p0 + p1;
                s1 += p2 + p3;
            }
            s0 += __shfl_xor_sync(0xffffffffu, s0, 1);
            s0 += __shfl_xor_sync(0xffffffffu, s0, 2);
            s1 += __shfl_xor_sync(0xffffffffu, s1, 1);
            s1 += __shfl_xor_sync(0xffffffffu, s1, 2);
            lr0 = lr0 * al0 + s0;
            lr1 = lr1 * al1 + s1;
            mr0 = mn0; mr1 = mn1;

#pragma unroll
            for (int n = 0; n < 8; n++) {
                oacc[n][0] *= al0; oacc[n][1] *= al0;
                oacc[n][2] *= al1; oacc[n][3] *= al1;
            }

            // ---- write P (permuted, warp-private rows) ----
            const int p0off = (l4 < 2) ? 4 * l4 : 4 * l4 - 7;
#pragma unroll
            for (int n = 0; n < 8; n++) {
                uint32_t* r0p = Ps + lrow0 * PSTR + n * 8 + p0off;
                uint32_t* r1p = Ps + lrow1 * PSTR + n * 8 + p0off;
                r0p[0] = f2t(sacc[n][0]); r0p[2] = f2t(sacc[n][1]);
                r1p[0] = f2t(sacc[n][2]); r1p[2] = f2t(sacc[n][3]);
            }
            __syncwarp();

            // ---- O += P @ V ----
#pragma unroll
            for (int kk = 0; kk < 8; kk++) {
                uint2 a01 = *(const uint2*)(Ps + lrow0 * PSTR + kk * 8 + 2 * l4);
                uint2 a23 = *(const uint2*)(Ps + lrow1 * PSTR + kk * 8 + 2 * l4);
                uint32_t a[4] = {a01.x, a23.x, a01.y, a23.y};
                const uint32_t* vb0 = Vs + (kk * 8 + l4) * VSTR + l2;
                const uint32_t* vb1 = vb0 + 4 * VSTR;
#pragma unroll
                for (int n = 0; n < 8; n++) {
                    uint32_t bb[2] = {vb0[n * 8], vb1[n * 8]};
                    mma8(oacc[n], a, bb);
                }
            }
            __syncwarp();
        }
    }

    const float inv0 = 1.f / lr0, inv1 = 1.f / lr1;
    const size_t ob0 = ((size_t)(b * SEQ + q0 + lrow0)) * DIM + h * HDIM;
    const size_t ob1 = ((size_t)(b * SEQ + q0 + lrow1)) * DIM + h * HDIM;
#pragma unroll
    for (int n = 0; n < 8; n++) {
        int col = n * 8 + 2 * l4;
        *(float2*)&Ctx[ob0 + col] = make_float2(__uint_as_float(f2t(oacc[n][0] * inv0)),
                                                __uint_as_float(f2t(oacc[n][1] * inv0)));
        *(float2*)&Ctx[ob1 + col] = make_float2(__uint_as_float(f2t(oacc[n][2] * inv1)),
                                                __uint_as_float(f2t(oacc[n][3] * inv1)));
    }
}

// ---------------- host launcher ----------------
extern "C" void kernel_launch(void* const* d_in, const int* in_sizes, int n_in,
                              void* d_out, int out_size)
{
    const float* x     = (const float*)d_in[0];
    // d_in[1] = mask (causal, hard-coded)
    const float* w_kvc = (const float*)d_in[2];
    const float* b_kvc = (const float*)d_in[3];
    const float* w_kvu = (const float*)d_in[4];
    const float* b_kvu = (const float*)d_in[5];
    const float* w_qc  = (const float*)d_in[6];
    const float* b_qc  = (const float*)d_in[7];
    const float* w_qu  = (const float*)d_in[8];
    const float* b_qu  = (const float*)d_in[9];
    const float* w_o   = (const float*)d_in[10];
    const float* b_o   = (const float*)d_in[11];
    float* out = (float*)d_out;

    float *lat, *kvup, *qc, *q, *ctx;
    uint32_t *xt, *wkvc, *wqc, *wkvu, *wqu, *wo;
    cudaGetSymbolAddress((void**)&lat,  g_lat);
    cudaGetSymbolAddress((void**)&kvup, g_kvup);
    cudaGetSymbolAddress((void**)&qc,   g_qc);
    cudaGetSymbolAddress((void**)&q,    g_q);
    cudaGetSymbolAddress((void**)&ctx,  g_ctx);
    cudaGetSymbolAddress((void**)&xt,   g_xt);
    cudaGetSymbolAddress((void**)&wkvc, g_wkvc);
    cudaGetSymbolAddress((void**)&wqc,  g_wqc);
    cudaGetSymbolAddress((void**)&wkvu, g_wkvu);
    cudaGetSymbolAddress((void**)&wqu,  g_wqu);
    cudaGetSymbolAddress((void**)&wo,   g_wo);

    cudaFuncSetAttribute(flash_tf32_kernel, cudaFuncAttributeMaxDynamicSharedMemorySize, FL_SMEM);

    // tile counts: (K/32)*(N/32)
    const int t0 = (DIM / 32) * (LATENT / 32);      // w_kvc  128
    const int t1 = (DIM / 32) * (QRANK / 32);       // w_qc   256
    const int t2 = (LATENT / 32) * (2 * DIM / 32);  // w_kvu  256
    const int t3 = (QRANK / 32) * (DIM / 32);       // w_qu   256
    const int t4 = (DIM / 32) * (DIM / 32);         // w_o   1024
    // launch 0: all weight transpose+converts
    cvt_wT_kernel<<<t0 + t1 + t2 + t3 + t4, 256>>>(
        w_kvc, wkvc, DIM, LATENT, t0,
        w_qc,  wqc,  DIM, QRANK,  t1,
        w_kvu, wkvu, LATENT, 2 * DIM, t2,
        w_qu,  wqu,  QRANK, DIM, t3,
        w_o,   wo,   DIM, DIM);
    // launch 1: x convert
    cvt_x_kernel<<<(T_TOK * DIM / 4 + 255) / 256, 256>>>((const float4*)x, (uint4*)xt, T_TOK * DIM / 4);

    // launch 2: fused kv_latent [8192,128] + q_c [8192,256], tf32-out
    fused_latqc_kernel<<<dim3(3, T_TOK / 128), 256, GEMM_SMEM>>>(
        xt, wkvc, b_kvc, lat, wqc, b_qc, qc);
    // launch 3: kv_up = lat @ w_kvu + b  [8192,2048] tf32-out
    gemm_tt_kernel<1><<<dim3(2 * DIM / 128, T_TOK / 128), 256, GEMM_SMEM>>>(
        (const uint32_t*)lat, wkvu, b_kvu, kvup, 2 * DIM, LATENT, 1.f);
    // launch 4: Q = q_c @ w_qu + b  [8192,1024] tf32-out * (log2e/8)
    gemm_tt_kernel<1><<<dim3(DIM / 128, T_TOK / 128), 256, GEMM_SMEM>>>(
        (const uint32_t*)qc, wqu, b_qu, q, DIM, QRANK, QSCALE);
    // launch 5: causal flash attention -> ctx (tf32-out)  [ncu -s 5 captures this]
    flash_tf32_kernel<<<dim3(SEQ / BQ, NHEADS, NBATCH), 256, FL_SMEM>>>(
        (const uint32_t*)q, (const uint32_t*)kvup, ctx);
    // launch 6: out = ctx @ w_o + b  [8192,1024] fp32
    gemm_tt_kernel<0><<<dim3(DIM / 128, T_TOK / 128), 256, GEMM_SMEM>>>(
        (const uint32_t*)ctx, wo, b_o, out, DIM, DIM, 1.f);
}